// round 4
// baseline (speedup 1.0000x reference)
#include <cuda_runtime.h>
#include <cuda_bf16.h>
#include <cstdint>

// Problem constants (fixed shapes from reference)
#define BATCH   2
#define SEQ     4096
#define DIM     1024
#define NHEADS  64
#define DHEAD   64
#define INNER   (NHEADS * DHEAD)     // 4096
#define MTOK    (BATCH * SEQ)        // 8192
#define SCALE_Q 0.125f               // 64^-0.5
#define EPS     1e-6f

// Scratch (device globals: allowed, not a runtime allocation)
__device__ float g_q[(size_t)MTOK * INNER];
__device__ float g_k[(size_t)MTOK * INNER];
__device__ float g_v[(size_t)MTOK * INNER];
__device__ float g_mid[(size_t)MTOK * INNER];

// ---------------------------------------------------------------------------
// SGEMM: C[M,N] = A[M,K] @ B[K,N] (+ epilogue). Row-major everywhere.
// 128x128 block tile, BK=8, 256 threads, 8x8 per-thread micro-tile.
// EPI: 0 = identity, 1 = relu, 2 = relu*SCALE_Q, 3 = +bias
// Requires M%128==0, N%128==0, K%8==0 (true for all our shapes).
// ---------------------------------------------------------------------------
template<int EPI>
__global__ __launch_bounds__(256)
void sgemm128(const float* __restrict__ A, const float* __restrict__ B,
              float* __restrict__ C, int M, int N, int K,
              const float* __restrict__ bias)
{
    __shared__ float As[8][128];
    __shared__ float Bs[8][128];

    const int tid = threadIdx.x;
    const int bm  = blockIdx.y * 128;
    const int bn  = blockIdx.x * 128;
    const int tx  = tid & 15;     // 0..15 -> column group
    const int ty  = tid >> 4;     // 0..15 -> row group

    // A tile load: 128 rows x 8 k, one float4 along K per thread
    const int arow = tid >> 1;           // 0..127
    const int acol = (tid & 1) * 4;      // 0 or 4
    // B tile load: 8 k x 128 n, one float4 along N per thread
    const int brow = tid >> 5;           // 0..7
    const int bcol = (tid & 31) * 4;     // 0..124

    const float* Aptr = A + (size_t)(bm + arow) * K + acol;
    const float* Bptr = B + (size_t)brow * N + bn + bcol;

    float acc[8][8];
    #pragma unroll
    for (int i = 0; i < 8; i++)
        #pragma unroll
        for (int j = 0; j < 8; j++) acc[i][j] = 0.f;

    for (int k0 = 0; k0 < K; k0 += 8) {
        float4 av = *reinterpret_cast<const float4*>(Aptr);
        float4 bv = *reinterpret_cast<const float4*>(Bptr);
        As[acol + 0][arow] = av.x;
        As[acol + 1][arow] = av.y;
        As[acol + 2][arow] = av.z;
        As[acol + 3][arow] = av.w;
        *reinterpret_cast<float4*>(&Bs[brow][bcol]) = bv;
        __syncthreads();

        #pragma unroll
        for (int kk = 0; kk < 8; kk++) {
            float a[8], b[8];
            *reinterpret_cast<float4*>(a)     = *reinterpret_cast<const float4*>(&As[kk][ty * 8]);
            *reinterpret_cast<float4*>(a + 4) = *reinterpret_cast<const float4*>(&As[kk][ty * 8 + 4]);
            *reinterpret_cast<float4*>(b)     = *reinterpret_cast<const float4*>(&Bs[kk][tx * 8]);
            *reinterpret_cast<float4*>(b + 4) = *reinterpret_cast<const float4*>(&Bs[kk][tx * 8 + 4]);
            #pragma unroll
            for (int i = 0; i < 8; i++)
                #pragma unroll
                for (int j = 0; j < 8; j++)
                    acc[i][j] += a[i] * b[j];
        }
        __syncthreads();

        Aptr += 8;
        Bptr += (size_t)8 * N;
    }

    // Epilogue with vectorized stores
    #pragma unroll
    for (int i = 0; i < 8; i++) {
        const int row = bm + ty * 8 + i;
        float* crow = C + (size_t)row * N + bn + tx * 8;
        float vals[8];
        #pragma unroll
        for (int j = 0; j < 8; j++) {
            float v = acc[i][j];
            if (EPI == 1) v = fmaxf(v, 0.f);
            if (EPI == 2) v = fmaxf(v, 0.f) * SCALE_Q;
            if (EPI == 3) v += bias[bn + tx * 8 + j];
            vals[j] = v;
        }
        *reinterpret_cast<float4*>(crow)     = *reinterpret_cast<float4*>(vals);
        *reinterpret_cast<float4*>(crow + 4) = *reinterpret_cast<float4*>(vals + 4);
    }
}

// ---------------------------------------------------------------------------
// Per-token stage. One block per token (8192 blocks, 256 threads).
//   w[d]    = sum_i k[i,d]
//   qw[i,d] = q[i,d] * w[d]                (q already relu*scaled)
//   norm[i] = sum_d qw[i,d]
//   out[i,j]= sum_d qw[i,d] * v[j,d] / (norm[i] + eps)
// ---------------------------------------------------------------------------
__global__ __launch_bounds__(256)
void perf_mid_kernel()
{
    __shared__ float sq[64 * 65];   // padded to kill bank conflicts
    __shared__ float sv[64 * 65];
    __shared__ float w[64];
    __shared__ float norm[64];

    const int t   = blockIdx.x;
    const int tid = threadIdx.x;
    const float* qt = g_q + (size_t)t * INNER;
    const float* kt = g_k + (size_t)t * INNER;
    const float* vt = g_v + (size_t)t * INNER;
    float*       ot = g_mid + (size_t)t * INNER;

    // Load q, v into padded shared
    for (int idx = tid; idx < 4096; idx += 256) {
        const int i = idx >> 6, d = idx & 63;
        sq[i * 65 + d] = qt[idx];
        sv[i * 65 + d] = vt[idx];
    }
    // w[d] = sum_i k[i,d]  (coalesced: 64 threads read consecutive d)
    if (tid < 64) {
        float s = 0.f;
        #pragma unroll 8
        for (int i = 0; i < 64; i++) s += kt[i * 64 + tid];
        w[tid] = s;
    }
    __syncthreads();

    // qw in-place
    for (int idx = tid; idx < 4096; idx += 256) {
        const int i = idx >> 6, d = idx & 63;
        sq[i * 65 + d] *= w[d];
    }
    __syncthreads();

    // norm[i]
    if (tid < 64) {
        float s = 0.f;
        #pragma unroll 8
        for (int d = 0; d < 64; d++) s += sq[tid * 65 + d];
        norm[tid] = s;
    }
    __syncthreads();

    // out[i,j]: lane = j (coalesced writes, conflict-free sv reads)
    const int j  = tid & 63;
    const int i0 = tid >> 6;  // 0..3
    #pragma unroll
    for (int ii = 0; ii < 16; ii++) {
        const int i = i0 * 16 + ii;
        float acc = 0.f;
        #pragma unroll
        for (int d = 0; d < 64; d++)
            acc += sq[i * 65 + d] * sv[j * 65 + d];
        ot[i * 64 + j] = acc / (norm[i] + EPS);
    }
}

// ---------------------------------------------------------------------------
extern "C" void kernel_launch(void* const* d_in, const int* in_sizes, int n_in,
                              void* d_out, int out_size)
{
    const float* x  = (const float*)d_in[0];
    const float* Wq = (const float*)d_in[1];
    const float* Wk = (const float*)d_in[2];
    const float* Wv = (const float*)d_in[3];
    const float* Wo = (const float*)d_in[4];
    const float* bo = (const float*)d_in[5];
    float* out = (float*)d_out;

    float *qp, *kp, *vp, *midp;
    cudaGetSymbolAddress((void**)&qp,   g_q);
    cudaGetSymbolAddress((void**)&kp,   g_k);
    cudaGetSymbolAddress((void**)&vp,   g_v);
    cudaGetSymbolAddress((void**)&midp, g_mid);

    dim3 block(256);
    dim3 gridQKV(INNER / 128, MTOK / 128);   // 32 x 64
    dim3 gridOut(DIM / 128, MTOK / 128);     //  8 x 64

    // Stage 1: QKV projections with fused activations
    sgemm128<2><<<gridQKV, block>>>(x, Wq, qp, MTOK, INNER, DIM, nullptr); // relu * scale
    sgemm128<1><<<gridQKV, block>>>(x, Wk, kp, MTOK, INNER, DIM, nullptr); // relu
    sgemm128<0><<<gridQKV, block>>>(x, Wv, vp, MTOK, INNER, DIM, nullptr); // identity

    // Stage 2: per-token collapsed "attention"
    perf_mid_kernel<<<MTOK, block>>>();

    // Stage 3: output projection + bias
    sgemm128<3><<<gridOut, block>>>(midp, Wo, out, MTOK, DIM, INNER, bo);
}

// round 8
// speedup vs baseline: 3.1138x; 3.1138x over previous
#include <cuda_runtime.h>
#include <cuda_bf16.h>
#include <cstdint>

// ---------------------------------------------------------------------------
// Problem constants
// ---------------------------------------------------------------------------
#define BATCH   2
#define SEQ     4096
#define DIM     1024
#define NHEADS  64
#define DHEAD   64
#define INNER   (NHEADS * DHEAD)     // 4096
#define MTOK    (BATCH * SEQ)        // 8192
#define SCALE_Q 0.125f
#define EPS     1e-6f

// ---------------------------------------------------------------------------
// Device scratch (static globals allowed; runtime allocation is not)
// ---------------------------------------------------------------------------
__device__ __align__(128) __nv_bfloat16 g_xhi[(size_t)MTOK * DIM];
__device__ __align__(128) __nv_bfloat16 g_xlo[(size_t)MTOK * DIM];
__device__ __align__(128) __nv_bfloat16 g_wqh[(size_t)INNER * DIM];   // [N][K]
__device__ __align__(128) __nv_bfloat16 g_wql[(size_t)INNER * DIM];
__device__ __align__(128) __nv_bfloat16 g_wkh[(size_t)INNER * DIM];
__device__ __align__(128) __nv_bfloat16 g_wkl[(size_t)INNER * DIM];
__device__ __align__(128) __nv_bfloat16 g_wvh[(size_t)INNER * DIM];
__device__ __align__(128) __nv_bfloat16 g_wvl[(size_t)INNER * DIM];
__device__ __align__(128) __nv_bfloat16 g_woh[(size_t)DIM * INNER];   // [1024][4096]
__device__ __align__(128) __nv_bfloat16 g_wol[(size_t)DIM * INNER];
__device__ __align__(128) float g_q[(size_t)MTOK * INNER];
__device__ __align__(128) float g_k[(size_t)MTOK * INNER];
__device__ __align__(128) float g_v[(size_t)MTOK * INNER];
__device__ __align__(128) __nv_bfloat16 g_mh[(size_t)MTOK * INNER];
__device__ __align__(128) __nv_bfloat16 g_ml[(size_t)MTOK * INNER];

// ---------------------------------------------------------------------------
// PTX helpers (all plain sm_80+/sm_75+ instructions — no 'a'-features)
// ---------------------------------------------------------------------------
__device__ __forceinline__ uint32_t smem_u32(const void* p) {
    uint32_t a;
    asm("{ .reg .u64 t; cvta.to.shared.u64 t, %1; cvt.u32.u64 %0, t; }"
        : "=r"(a) : "l"(p));
    return a;
}

#define CP_ASYNC16(dst, src) \
    asm volatile("cp.async.cg.shared.global [%0], [%1], 16;" :: "r"(dst), "l"(src) : "memory")
#define CP_COMMIT() asm volatile("cp.async.commit_group;" ::: "memory")
#define CP_WAIT(n)  asm volatile("cp.async.wait_group %0;" :: "n"(n) : "memory")

#define LDSM4(r, addr) \
    asm volatile("ldmatrix.sync.aligned.m8n8.x4.shared.b16 {%0,%1,%2,%3}, [%4];" \
        : "=r"((r)[0]), "=r"((r)[1]), "=r"((r)[2]), "=r"((r)[3]) : "r"(addr))

__device__ __forceinline__ void mma16816(float* d, const uint32_t* a, const uint32_t* b) {
    asm volatile(
        "mma.sync.aligned.m16n8k16.row.col.f32.bf16.bf16.f32 "
        "{%0,%1,%2,%3}, {%4,%5,%6,%7}, {%8,%9}, {%0,%1,%2,%3};"
        : "+f"(d[0]), "+f"(d[1]), "+f"(d[2]), "+f"(d[3])
        : "r"(a[0]), "r"(a[1]), "r"(a[2]), "r"(a[3]), "r"(b[0]), "r"(b[1]));
}

__device__ __forceinline__ void split_bf16(float v, __nv_bfloat16& h, __nv_bfloat16& l) {
    h = __float2bfloat16_rn(v);
    l = __float2bfloat16_rn(v - __bfloat162float(h));
}

// ---------------------------------------------------------------------------
// Split-bf16 GEMM on HMMA (mma.sync):
//   C[M,N] fp32 = (Ahi+Alo)[M,K] @ (Bhi+Blo)[N,K]^T
// BM=BN=128, BK=64 (128B swizzled rows), 2-stage cp.async pipeline.
// 256 threads, 8 warps as 4(m) x 2(n); warp tile 32x64.
// EPI: 0 identity, 1 relu, 2 relu*SCALE_Q, 3 +bias
// ---------------------------------------------------------------------------
#define BM 128
#define BN 128
#define BK 64
#define TILE_B  (128 * 128)           // 16384 bytes per (rows x 128B) tile
#define STAGE_B (4 * TILE_B)          // Ahi, Alo, Bhi, Blo
#define GEMM_SMEM (2 * STAGE_B)       // 131072

template<int EPI>
__global__ __launch_bounds__(256, 1)
void gemm_split(const __nv_bfloat16* __restrict__ Ahi, const __nv_bfloat16* __restrict__ Alo,
                const __nv_bfloat16* __restrict__ Bhi, const __nv_bfloat16* __restrict__ Blo,
                float* __restrict__ C, const float* __restrict__ bias,
                int M, int N, int K)
{
    extern __shared__ char smem[];
    const uint32_t sb = smem_u32(smem);
    const int tid  = threadIdx.x;
    const int wid  = tid >> 5;
    const int lane = tid & 31;
    const int bm = blockIdx.y * BM;
    const int bn = blockIdx.x * BN;
    const int wm = (wid & 3) * 32;    // warp m offset within tile
    const int wn = (wid >> 2) * 64;   // warp n offset within tile
    const int nchunk = K / BK;

    // Source row-base pointers per tile {Ahi, Alo, Bhi, Blo}
    const __nv_bfloat16* tsrc[4];
    tsrc[0] = Ahi + (size_t)bm * K;
    tsrc[1] = Alo + (size_t)bm * K;
    tsrc[2] = Bhi + (size_t)bn * K;
    tsrc[3] = Blo + (size_t)bn * K;

    // ---- async tile loader: 128 rows x 8 granules(16B) per tile ----
    const int lg  = tid & 7;          // granule 0..7 (16B each = 8 bf16)
    const int lr0 = tid >> 3;         // row 0..31 (+j*32)
    auto load_chunk = [&](int st, int c) {
        #pragma unroll
        for (int tile = 0; tile < 4; tile++) {
            const uint32_t dbase = sb + st * STAGE_B + tile * TILE_B;
            const __nv_bfloat16* s = tsrc[tile] + (size_t)c * BK + lg * 8;
            #pragma unroll
            for (int j = 0; j < 4; j++) {
                const int r = lr0 + j * 32;
                CP_ASYNC16(dbase + r * 128 + ((lg ^ (r & 7)) << 4),
                           s + (size_t)r * K);
            }
        }
        CP_COMMIT();
    };

    float acc[2][8][4];
    #pragma unroll
    for (int mi = 0; mi < 2; mi++)
        #pragma unroll
        for (int ni = 0; ni < 8; ni++)
            #pragma unroll
            for (int v = 0; v < 4; v++) acc[mi][ni][v] = 0.f;

    load_chunk(0, 0);

    // ldmatrix lane addressing (constant per thread, within a k-step)
    const int a_row = wm + (lane & 15);           // + mi*16
    const int a_kg  = lane >> 4;                  // +2*kk  (granule units of 8 elems)
    const int b_row = wn + (lane & 7) + ((lane >> 4) << 3);  // + p*16
    const int b_kg  = (lane >> 3) & 1;            // +2*kk

    for (int c = 0; c < nchunk; c++) {
        if (c + 1 < nchunk) { load_chunk((c + 1) & 1, c + 1); CP_WAIT(1); }
        else                { CP_WAIT(0); }
        __syncthreads();

        const uint32_t sA_hi = sb + (c & 1) * STAGE_B;
        const uint32_t sA_lo = sA_hi + TILE_B;
        const uint32_t sB_hi = sA_hi + 2 * TILE_B;
        const uint32_t sB_lo = sA_hi + 3 * TILE_B;

        #pragma unroll
        for (int kk = 0; kk < 4; kk++) {           // 4 x k16 per chunk
            uint32_t ahi[2][4], alo[2][4];
            #pragma unroll
            for (int mi = 0; mi < 2; mi++) {
                const int r = a_row + mi * 16;
                const int kg = 2 * kk + a_kg;
                const uint32_t off = r * 128 + ((kg ^ (r & 7)) << 4);
                LDSM4(ahi[mi], sA_hi + off);
                LDSM4(alo[mi], sA_lo + off);
            }
            uint32_t bhi[8][2], blo[8][2];
            #pragma unroll
            for (int p = 0; p < 4; p++) {          // pair of n8 tiles per x4
                const int r = b_row + p * 16;
                const int kg = 2 * kk + b_kg;
                const uint32_t off = r * 128 + ((kg ^ (r & 7)) << 4);
                uint32_t t[4];
                LDSM4(t, sB_hi + off);
                bhi[p * 2][0] = t[0]; bhi[p * 2][1] = t[1];
                bhi[p * 2 + 1][0] = t[2]; bhi[p * 2 + 1][1] = t[3];
                LDSM4(t, sB_lo + off);
                blo[p * 2][0] = t[0]; blo[p * 2][1] = t[1];
                blo[p * 2 + 1][0] = t[2]; blo[p * 2 + 1][1] = t[3];
            }
            #pragma unroll
            for (int mi = 0; mi < 2; mi++)
                #pragma unroll
                for (int ni = 0; ni < 8; ni++) {
                    mma16816(acc[mi][ni], ahi[mi], bhi[ni]);  // hi*hi
                    mma16816(acc[mi][ni], ahi[mi], blo[ni]);  // hi*lo
                    mma16816(acc[mi][ni], alo[mi], bhi[ni]);  // lo*hi
                }
        }
        __syncthreads();
    }

    // ---- epilogue ----
    const int erow = bm + wm + (lane >> 2);
    const int ecol0 = bn + wn + (lane & 3) * 2;
    #pragma unroll
    for (int mi = 0; mi < 2; mi++) {
        #pragma unroll
        for (int ni = 0; ni < 8; ni++) {
            const int row = erow + mi * 16;
            const int col = ecol0 + ni * 8;
            float v[4] = { acc[mi][ni][0], acc[mi][ni][1],
                           acc[mi][ni][2], acc[mi][ni][3] };
            if (EPI == 1) {
                #pragma unroll
                for (int q = 0; q < 4; q++) v[q] = fmaxf(v[q], 0.f);
            }
            if (EPI == 2) {
                #pragma unroll
                for (int q = 0; q < 4; q++) v[q] = fmaxf(v[q], 0.f) * SCALE_Q;
            }
            if (EPI == 3) {
                const float b0 = __ldg(&bias[col]), b1 = __ldg(&bias[col + 1]);
                v[0] += b0; v[1] += b1; v[2] += b0; v[3] += b1;
            }
            *reinterpret_cast<float2*>(C + (size_t)row * N + col) =
                make_float2(v[0], v[1]);
            *reinterpret_cast<float2*>(C + (size_t)(row + 8) * N + col) =
                make_float2(v[2], v[3]);
        }
    }
}

// ---------------------------------------------------------------------------
// Conversion kernels
// ---------------------------------------------------------------------------
__global__ __launch_bounds__(256)
void split_fp32(const float* __restrict__ in, __nv_bfloat16* __restrict__ hi,
                __nv_bfloat16* __restrict__ lo, int n)
{
    const int i = (blockIdx.x * 256 + threadIdx.x) * 4;
    if (i >= n) return;
    const float4 v = *reinterpret_cast<const float4*>(in + i);
    __nv_bfloat16 h0, h1, h2, h3, l0, l1, l2, l3;
    split_bf16(v.x, h0, l0); split_bf16(v.y, h1, l1);
    split_bf16(v.z, h2, l2); split_bf16(v.w, h3, l3);
    __nv_bfloat162* ph = reinterpret_cast<__nv_bfloat162*>(hi + i);
    __nv_bfloat162* pl = reinterpret_cast<__nv_bfloat162*>(lo + i);
    ph[0] = __halves2bfloat162(h0, h1); ph[1] = __halves2bfloat162(h2, h3);
    pl[0] = __halves2bfloat162(l0, l1); pl[1] = __halves2bfloat162(l2, l3);
}

// W[K][N] fp32 -> T_hi/T_lo[N][K] bf16 (transpose + split)
__global__ __launch_bounds__(256)
void transpose_split(const float* __restrict__ W, __nv_bfloat16* __restrict__ Th,
                     __nv_bfloat16* __restrict__ Tl, int K, int N)
{
    __shared__ float tile[32][33];
    const int n0 = blockIdx.x * 32, k0 = blockIdx.y * 32;
    const int tx = threadIdx.x, ty = threadIdx.y;
    #pragma unroll
    for (int j = 0; j < 4; j++)
        tile[ty + j * 8][tx] = W[(size_t)(k0 + ty + j * 8) * N + n0 + tx];
    __syncthreads();
    #pragma unroll
    for (int j = 0; j < 4; j++) {
        const int n = n0 + ty + j * 8, k = k0 + tx;
        __nv_bfloat16 h, l;
        split_bf16(tile[tx][ty + j * 8], h, l);
        Th[(size_t)n * K + k] = h;
        Tl[(size_t)n * K + k] = l;
    }
}

// ---------------------------------------------------------------------------
// Per-token stage, 4x4 register-blocked; emits bf16 hi/lo directly.
//   w[d] = sum_i k[i,d];  qw = q*w;  norm[i] = sum_d qw[i,d]
//   mid[i,j] = sum_d qw[i,d]*v[j,d] / (norm[i]+eps)
// ---------------------------------------------------------------------------
__global__ __launch_bounds__(256)
void perf_mid_kernel()
{
    __shared__ float sq[64 * 65];
    __shared__ float sv[64 * 65];
    __shared__ float w[64];
    __shared__ float rnorm[64];

    const int t   = blockIdx.x;
    const int tid = threadIdx.x;
    const float* qt = g_q + (size_t)t * INNER;
    const float* kt = g_k + (size_t)t * INNER;
    const float* vt = g_v + (size_t)t * INNER;

    for (int idx = tid; idx < 4096; idx += 256) {
        const int i = idx >> 6, d = idx & 63;
        sq[i * 65 + d] = qt[idx];
        sv[i * 65 + d] = vt[idx];
    }
    if (tid < 64) {
        float s = 0.f;
        #pragma unroll 8
        for (int i = 0; i < 64; i++) s += kt[i * 64 + tid];
        w[tid] = s;
    }
    __syncthreads();

    for (int idx = tid; idx < 4096; idx += 256) {
        const int i = idx >> 6, d = idx & 63;
        sq[i * 65 + d] *= w[d];
    }
    __syncthreads();

    if (tid < 64) {
        float s = 0.f;
        #pragma unroll 8
        for (int d = 0; d < 64; d++) s += sq[tid * 65 + d];
        rnorm[tid] = 1.f / (s + EPS);
    }
    __syncthreads();

    const int ti = tid >> 4, tj = tid & 15;
    const int i0 = ti * 4, j0 = tj * 4;
    float acc[4][4];
    #pragma unroll
    for (int r = 0; r < 4; r++)
        #pragma unroll
        for (int c = 0; c < 4; c++) acc[r][c] = 0.f;

    #pragma unroll 4
    for (int d = 0; d < 64; d++) {
        float a[4], b[4];
        #pragma unroll
        for (int r = 0; r < 4; r++) a[r] = sq[(i0 + r) * 65 + d];
        #pragma unroll
        for (int c = 0; c < 4; c++) b[c] = sv[(j0 + c) * 65 + d];
        #pragma unroll
        for (int r = 0; r < 4; r++)
            #pragma unroll
            for (int c = 0; c < 4; c++) acc[r][c] += a[r] * b[c];
    }

    __nv_bfloat16* mh = g_mh + (size_t)t * INNER;
    __nv_bfloat16* ml = g_ml + (size_t)t * INNER;
    #pragma unroll
    for (int r = 0; r < 4; r++) {
        const int i = i0 + r;
        const float rn_ = rnorm[i];
        __nv_bfloat16 h[4], l[4];
        #pragma unroll
        for (int c = 0; c < 4; c++) split_bf16(acc[r][c] * rn_, h[c], l[c]);
        __nv_bfloat162* ph = reinterpret_cast<__nv_bfloat162*>(mh + i * 64 + j0);
        __nv_bfloat162* pl = reinterpret_cast<__nv_bfloat162*>(ml + i * 64 + j0);
        ph[0] = __halves2bfloat162(h[0], h[1]); ph[1] = __halves2bfloat162(h[2], h[3]);
        pl[0] = __halves2bfloat162(l[0], l[1]); pl[1] = __halves2bfloat162(l[2], l[3]);
    }
}

// ---------------------------------------------------------------------------
extern "C" void kernel_launch(void* const* d_in, const int* in_sizes, int n_in,
                              void* d_out, int out_size)
{
    const float* x  = (const float*)d_in[0];
    const float* Wq = (const float*)d_in[1];
    const float* Wk = (const float*)d_in[2];
    const float* Wv = (const float*)d_in[3];
    const float* Wo = (const float*)d_in[4];
    const float* bo = (const float*)d_in[5];
    float* out = (float*)d_out;

    __nv_bfloat16 *xhi, *xlo, *wqh, *wql, *wkh, *wkl, *wvh, *wvl, *woh, *wol, *mh, *ml;
    float *qp, *kp, *vp;
    cudaGetSymbolAddress((void**)&xhi, g_xhi); cudaGetSymbolAddress((void**)&xlo, g_xlo);
    cudaGetSymbolAddress((void**)&wqh, g_wqh); cudaGetSymbolAddress((void**)&wql, g_wql);
    cudaGetSymbolAddress((void**)&wkh, g_wkh); cudaGetSymbolAddress((void**)&wkl, g_wkl);
    cudaGetSymbolAddress((void**)&wvh, g_wvh); cudaGetSymbolAddress((void**)&wvl, g_wvl);
    cudaGetSymbolAddress((void**)&woh, g_woh); cudaGetSymbolAddress((void**)&wol, g_wol);
    cudaGetSymbolAddress((void**)&mh,  g_mh);  cudaGetSymbolAddress((void**)&ml,  g_ml);
    cudaGetSymbolAddress((void**)&qp,  g_q);
    cudaGetSymbolAddress((void**)&kp,  g_k);
    cudaGetSymbolAddress((void**)&vp,  g_v);

    cudaFuncSetAttribute(gemm_split<0>, cudaFuncAttributeMaxDynamicSharedMemorySize, GEMM_SMEM);
    cudaFuncSetAttribute(gemm_split<1>, cudaFuncAttributeMaxDynamicSharedMemorySize, GEMM_SMEM);
    cudaFuncSetAttribute(gemm_split<2>, cudaFuncAttributeMaxDynamicSharedMemorySize, GEMM_SMEM);
    cudaFuncSetAttribute(gemm_split<3>, cudaFuncAttributeMaxDynamicSharedMemorySize, GEMM_SMEM);

    // Stage 0: hi/lo conversions
    split_fp32<<<(MTOK * DIM) / 1024, 256>>>(x, xhi, xlo, MTOK * DIM);
    dim3 tb(32, 8);
    transpose_split<<<dim3(INNER / 32, DIM / 32), tb>>>(Wq, wqh, wql, DIM, INNER);
    transpose_split<<<dim3(INNER / 32, DIM / 32), tb>>>(Wk, wkh, wkl, DIM, INNER);
    transpose_split<<<dim3(INNER / 32, DIM / 32), tb>>>(Wv, wvh, wvl, DIM, INNER);
    transpose_split<<<dim3(DIM / 32, INNER / 32), tb>>>(Wo, woh, wol, INNER, DIM);

    // Stage 1: QKV projections (HMMA split-bf16) with fused activations
    dim3 gQKV(INNER / BN, MTOK / BM);   // 32 x 64
    gemm_split<2><<<gQKV, 256, GEMM_SMEM>>>(xhi, xlo, wqh, wql, qp, nullptr, MTOK, INNER, DIM);
    gemm_split<1><<<gQKV, 256, GEMM_SMEM>>>(xhi, xlo, wkh, wkl, kp, nullptr, MTOK, INNER, DIM);
    gemm_split<0><<<gQKV, 256, GEMM_SMEM>>>(xhi, xlo, wvh, wvl, vp, nullptr, MTOK, INNER, DIM);

    // Stage 2: per-token collapsed attention (emits mid hi/lo)
    perf_mid_kernel<<<MTOK, 256>>>();

    // Stage 3: output projection + bias
    dim3 gOut(DIM / BN, MTOK / BM);     // 8 x 64
    gemm_split<3><<<gOut, 256, GEMM_SMEM>>>(mh, ml, woh, wol, out, bo, MTOK, DIM, INNER);
}

// round 13
// speedup vs baseline: 3.2473x; 1.0429x over previous
#include <cuda_runtime.h>
#include <cuda_bf16.h>
#include <cstdint>

// ---------------------------------------------------------------------------
// Problem constants
// ---------------------------------------------------------------------------
#define BATCH   2
#define SEQ     4096
#define DIM     1024
#define NHEADS  64
#define DHEAD   64
#define INNER   (NHEADS * DHEAD)     // 4096
#define MTOK    (BATCH * SEQ)        // 8192
#define SCALE_Q 0.125f
#define EPS     1e-6f

// ---------------------------------------------------------------------------
// Device scratch (static globals allowed; runtime allocation is not)
// ---------------------------------------------------------------------------
__device__ __align__(128) __nv_bfloat16 g_xhi[(size_t)MTOK * DIM];
__device__ __align__(128) __nv_bfloat16 g_xlo[(size_t)MTOK * DIM];
__device__ __align__(128) __nv_bfloat16 g_wqh[(size_t)INNER * DIM];   // [N][K]
__device__ __align__(128) __nv_bfloat16 g_wql[(size_t)INNER * DIM];
__device__ __align__(128) __nv_bfloat16 g_wkh[(size_t)INNER * DIM];
__device__ __align__(128) __nv_bfloat16 g_wkl[(size_t)INNER * DIM];
__device__ __align__(128) __nv_bfloat16 g_wvh[(size_t)INNER * DIM];
__device__ __align__(128) __nv_bfloat16 g_wvl[(size_t)INNER * DIM];
__device__ __align__(128) __nv_bfloat16 g_woh[(size_t)DIM * INNER];   // [1024][4096]
__device__ __align__(128) __nv_bfloat16 g_wol[(size_t)DIM * INNER];
__device__ __align__(128) float g_q[(size_t)MTOK * INNER];
__device__ __align__(128) float g_k[(size_t)MTOK * INNER];
__device__ __align__(128) float g_v[(size_t)MTOK * INNER];
__device__ __align__(128) __nv_bfloat16 g_mh[(size_t)MTOK * INNER];
__device__ __align__(128) __nv_bfloat16 g_ml[(size_t)MTOK * INNER];

// ---------------------------------------------------------------------------
// PTX helpers (plain sm_80+/sm_75+ — no 'a'-features; sm_103 target safe)
// ---------------------------------------------------------------------------
__device__ __forceinline__ uint32_t smem_u32(const void* p) {
    uint32_t a;
    asm("{ .reg .u64 t; cvta.to.shared.u64 t, %1; cvt.u32.u64 %0, t; }"
        : "=r"(a) : "l"(p));
    return a;
}

#define CP_ASYNC16(dst, src) \
    asm volatile("cp.async.cg.shared.global [%0], [%1], 16;" :: "r"(dst), "l"(src) : "memory")
#define CP_COMMIT() asm volatile("cp.async.commit_group;" ::: "memory")
#define CP_WAIT(n)  asm volatile("cp.async.wait_group %0;" :: "n"(n) : "memory")

#define LDSM4(r, addr) \
    asm volatile("ldmatrix.sync.aligned.m8n8.x4.shared.b16 {%0,%1,%2,%3}, [%4];" \
        : "=r"((r)[0]), "=r"((r)[1]), "=r"((r)[2]), "=r"((r)[3]) : "r"(addr))

__device__ __forceinline__ void mma16816(float* d, const uint32_t* a, const uint32_t* b) {
    asm volatile(
        "mma.sync.aligned.m16n8k16.row.col.f32.bf16.bf16.f32 "
        "{%0,%1,%2,%3}, {%4,%5,%6,%7}, {%8,%9}, {%0,%1,%2,%3};"
        : "+f"(d[0]), "+f"(d[1]), "+f"(d[2]), "+f"(d[3])
        : "r"(a[0]), "r"(a[1]), "r"(a[2]), "r"(a[3]), "r"(b[0]), "r"(b[1]));
}

__device__ __forceinline__ void split_bf16(float v, __nv_bfloat16& h, __nv_bfloat16& l) {
    h = __float2bfloat16_rn(v);
    l = __float2bfloat16_rn(v - __bfloat162float(h));
}

// ---------------------------------------------------------------------------
// Split-bf16 GEMM on HMMA (mma.sync):
//   C[M,N] fp32 = (Ahi+Alo)[M,K] @ (Bhi+Blo)[N,K]^T
// BM=128, BN=256, BK=64 (128B swizzled rows), 2-stage cp.async pipeline.
// 512 threads, 16 warps as 4(m) x 4(n); warp tile 32x64 (same micro-kernel
// as the R8 passing version).
// EPI: 0 identity, 1 relu, 2 relu*SCALE_Q, 3 +bias
// ---------------------------------------------------------------------------
#define BM 128
#define BN 256
#define BK 64
#define TILE_A_B (128 * 128)          // 16384 bytes (128 rows x 128B)
#define TILE_B_B (256 * 128)          // 32768 bytes (256 rows x 128B)
#define OFF_AHI 0
#define OFF_ALO (TILE_A_B)
#define OFF_BHI (2 * TILE_A_B)
#define OFF_BLO (2 * TILE_A_B + TILE_B_B)
#define STAGE_B (2 * TILE_A_B + 2 * TILE_B_B)   // 98304
#define GEMM_SMEM (2 * STAGE_B)                 // 196608

template<int EPI>
__global__ __launch_bounds__(512, 1)
void gemm_split(const __nv_bfloat16* __restrict__ Ahi, const __nv_bfloat16* __restrict__ Alo,
                const __nv_bfloat16* __restrict__ Bhi, const __nv_bfloat16* __restrict__ Blo,
                float* __restrict__ C, const float* __restrict__ bias,
                int M, int N, int K)
{
    extern __shared__ char smem[];
    const uint32_t sb = smem_u32(smem);
    const int tid  = threadIdx.x;
    const int wid  = tid >> 5;
    const int lane = tid & 31;
    const int bm = blockIdx.y * BM;
    const int bn = blockIdx.x * BN;
    const int wm = (wid & 3) * 32;    // warp m offset (4 groups over 128)
    const int wn = (wid >> 2) * 64;   // warp n offset (4 groups over 256)
    const int nchunk = K / BK;

    // Source row-base pointers per tile {Ahi, Alo, Bhi, Blo}
    const __nv_bfloat16* tsrc[4];
    tsrc[0] = Ahi + (size_t)bm * K;
    tsrc[1] = Alo + (size_t)bm * K;
    tsrc[2] = Bhi + (size_t)bn * K;
    tsrc[3] = Blo + (size_t)bn * K;

    // ---- async tile loader ----
    // 512 threads; granule = 16B (8 bf16). A tiles: 128 rows; B tiles: 256 rows.
    const int lg  = tid & 7;          // granule 0..7 within 128B row
    const int lr0 = tid >> 3;         // row 0..63 (+j*64)
    auto load_chunk = [&](int st, int c) {
        const uint32_t stbase = sb + st * STAGE_B;
        #pragma unroll
        for (int tile = 0; tile < 2; tile++) {       // A hi/lo: 128 rows each
            const uint32_t dbase = stbase + tile * TILE_A_B;
            const __nv_bfloat16* s = tsrc[tile] + (size_t)c * BK + lg * 8;
            #pragma unroll
            for (int j = 0; j < 2; j++) {
                const int r = lr0 + j * 64;
                CP_ASYNC16(dbase + r * 128 + ((lg ^ (r & 7)) << 4),
                           s + (size_t)r * K);
            }
        }
        #pragma unroll
        for (int tile = 2; tile < 4; tile++) {       // B hi/lo: 256 rows each
            const uint32_t dbase = stbase + OFF_BHI + (tile - 2) * TILE_B_B;
            const __nv_bfloat16* s = tsrc[tile] + (size_t)c * BK + lg * 8;
            #pragma unroll
            for (int j = 0; j < 4; j++) {
                const int r = lr0 + j * 64;
                CP_ASYNC16(dbase + r * 128 + ((lg ^ (r & 7)) << 4),
                           s + (size_t)r * K);
            }
        }
        CP_COMMIT();
    };

    float acc[2][8][4];
    #pragma unroll
    for (int mi = 0; mi < 2; mi++)
        #pragma unroll
        for (int ni = 0; ni < 8; ni++)
            #pragma unroll
            for (int v = 0; v < 4; v++) acc[mi][ni][v] = 0.f;

    load_chunk(0, 0);

    // ldmatrix lane addressing (constant per thread, within a k-step)
    const int a_row = wm + (lane & 15);                      // + mi*16
    const int a_kg  = lane >> 4;                             // +2*kk
    const int b_row = wn + (lane & 7) + ((lane >> 4) << 3);  // + p*16
    const int b_kg  = (lane >> 3) & 1;                       // +2*kk

    for (int c = 0; c < nchunk; c++) {
        if (c + 1 < nchunk) { load_chunk((c + 1) & 1, c + 1); CP_WAIT(1); }
        else                { CP_WAIT(0); }
        __syncthreads();

        const uint32_t stb  = sb + (c & 1) * STAGE_B;
        const uint32_t sA_hi = stb + OFF_AHI;
        const uint32_t sA_lo = stb + OFF_ALO;
        const uint32_t sB_hi = stb + OFF_BHI;
        const uint32_t sB_lo = stb + OFF_BLO;

        #pragma unroll
        for (int kk = 0; kk < 4; kk++) {           // 4 x k16 per chunk
            uint32_t ahi[2][4], alo[2][4];
            #pragma unroll
            for (int mi = 0; mi < 2; mi++) {
                const int r = a_row + mi * 16;
                const int kg = 2 * kk + a_kg;
                const uint32_t off = r * 128 + ((kg ^ (r & 7)) << 4);
                LDSM4(ahi[mi], sA_hi + off);
                LDSM4(alo[mi], sA_lo + off);
            }
            uint32_t bhi[8][2], blo[8][2];
            #pragma unroll
            for (int p = 0; p < 4; p++) {          // pair of n8 tiles per x4
                const int r = b_row + p * 16;
                const int kg = 2 * kk + b_kg;
                const uint32_t off = r * 128 + ((kg ^ (r & 7)) << 4);
                uint32_t t[4];
                LDSM4(t, sB_hi + off);
                bhi[p * 2][0] = t[0]; bhi[p * 2][1] = t[1];
                bhi[p * 2 + 1][0] = t[2]; bhi[p * 2 + 1][1] = t[3];
                LDSM4(t, sB_lo + off);
                blo[p * 2][0] = t[0]; blo[p * 2][1] = t[1];
                blo[p * 2 + 1][0] = t[2]; blo[p * 2 + 1][1] = t[3];
            }
            #pragma unroll
            for (int mi = 0; mi < 2; mi++)
                #pragma unroll
                for (int ni = 0; ni < 8; ni++) {
                    mma16816(acc[mi][ni], ahi[mi], bhi[ni]);  // hi*hi
                    mma16816(acc[mi][ni], ahi[mi], blo[ni]);  // hi*lo
                    mma16816(acc[mi][ni], alo[mi], bhi[ni]);  // lo*hi
                }
        }
        __syncthreads();
    }

    // ---- epilogue ----
    const int erow  = bm + wm + (lane >> 2);
    const int ecol0 = bn + wn + (lane & 3) * 2;
    #pragma unroll
    for (int mi = 0; mi < 2; mi++) {
        #pragma unroll
        for (int ni = 0; ni < 8; ni++) {
            const int row = erow + mi * 16;
            const int col = ecol0 + ni * 8;
            float v[4] = { acc[mi][ni][0], acc[mi][ni][1],
                           acc[mi][ni][2], acc[mi][ni][3] };
            if (EPI == 1) {
                #pragma unroll
                for (int q = 0; q < 4; q++) v[q] = fmaxf(v[q], 0.f);
            }
            if (EPI == 2) {
                #pragma unroll
                for (int q = 0; q < 4; q++) v[q] = fmaxf(v[q], 0.f) * SCALE_Q;
            }
            if (EPI == 3) {
                const float b0 = __ldg(&bias[col]), b1 = __ldg(&bias[col + 1]);
                v[0] += b0; v[1] += b1; v[2] += b0; v[3] += b1;
            }
            *reinterpret_cast<float2*>(C + (size_t)row * N + col) =
                make_float2(v[0], v[1]);
            *reinterpret_cast<float2*>(C + (size_t)(row + 8) * N + col) =
                make_float2(v[2], v[3]);
        }
    }
}

// ---------------------------------------------------------------------------
// Conversion kernels
// ---------------------------------------------------------------------------
__global__ __launch_bounds__(256)
void split_fp32(const float* __restrict__ in, __nv_bfloat16* __restrict__ hi,
                __nv_bfloat16* __restrict__ lo, int n)
{
    const int i = (blockIdx.x * 256 + threadIdx.x) * 4;
    if (i >= n) return;
    const float4 v = *reinterpret_cast<const float4*>(in + i);
    __nv_bfloat16 h0, h1, h2, h3, l0, l1, l2, l3;
    split_bf16(v.x, h0, l0); split_bf16(v.y, h1, l1);
    split_bf16(v.z, h2, l2); split_bf16(v.w, h3, l3);
    __nv_bfloat162* ph = reinterpret_cast<__nv_bfloat162*>(hi + i);
    __nv_bfloat162* pl = reinterpret_cast<__nv_bfloat162*>(lo + i);
    ph[0] = __halves2bfloat162(h0, h1); ph[1] = __halves2bfloat162(h2, h3);
    pl[0] = __halves2bfloat162(l0, l1); pl[1] = __halves2bfloat162(l2, l3);
}

// W[K][N] fp32 -> T_hi/T_lo[N][K] bf16 (transpose + split)
__global__ __launch_bounds__(256)
void transpose_split(const float* __restrict__ W, __nv_bfloat16* __restrict__ Th,
                     __nv_bfloat16* __restrict__ Tl, int K, int N)
{
    __shared__ float tile[32][33];
    const int n0 = blockIdx.x * 32, k0 = blockIdx.y * 32;
    const int tx = threadIdx.x, ty = threadIdx.y;
    #pragma unroll
    for (int j = 0; j < 4; j++)
        tile[ty + j * 8][tx] = W[(size_t)(k0 + ty + j * 8) * N + n0 + tx];
    __syncthreads();
    #pragma unroll
    for (int j = 0; j < 4; j++) {
        const int n = n0 + ty + j * 8, k = k0 + tx;
        __nv_bfloat16 h, l;
        split_bf16(tile[tx][ty + j * 8], h, l);
        Th[(size_t)n * K + k] = h;
        Tl[(size_t)n * K + k] = l;
    }
}

// ---------------------------------------------------------------------------
// Per-token stage, 4x4 register-blocked; emits bf16 hi/lo directly.
//   w[d] = sum_i k[i,d];  qw = q*w;  norm[i] = sum_d qw[i,d]
//   mid[i,j] = sum_d qw[i,d]*v[j,d] / (norm[i]+eps)
// ---------------------------------------------------------------------------
__global__ __launch_bounds__(256)
void perf_mid_kernel()
{
    __shared__ float sq[64 * 65];
    __shared__ float sv[64 * 65];
    __shared__ float w[64];
    __shared__ float rnorm[64];

    const int t   = blockIdx.x;
    const int tid = threadIdx.x;
    const float* qt = g_q + (size_t)t * INNER;
    const float* kt = g_k + (size_t)t * INNER;
    const float* vt = g_v + (size_t)t * INNER;

    for (int idx = tid; idx < 4096; idx += 256) {
        const int i = idx >> 6, d = idx & 63;
        sq[i * 65 + d] = qt[idx];
        sv[i * 65 + d] = vt[idx];
    }
    if (tid < 64) {
        float s = 0.f;
        #pragma unroll 8
        for (int i = 0; i < 64; i++) s += kt[i * 64 + tid];
        w[tid] = s;
    }
    __syncthreads();

    for (int idx = tid; idx < 4096; idx += 256) {
        const int i = idx >> 6, d = idx & 63;
        sq[i * 65 + d] *= w[d];
    }
    __syncthreads();

    if (tid < 64) {
        float s = 0.f;
        #pragma unroll 8
        for (int d = 0; d < 64; d++) s += sq[tid * 65 + d];
        rnorm[tid] = 1.f / (s + EPS);
    }
    __syncthreads();

    const int ti = tid >> 4, tj = tid & 15;
    const int i0 = ti * 4, j0 = tj * 4;
    float acc[4][4];
    #pragma unroll
    for (int r = 0; r < 4; r++)
        #pragma unroll
        for (int c = 0; c < 4; c++) acc[r][c] = 0.f;

    #pragma unroll 4
    for (int d = 0; d < 64; d++) {
        float a[4], b[4];
        #pragma unroll
        for (int r = 0; r < 4; r++) a[r] = sq[(i0 + r) * 65 + d];
        #pragma unroll
        for (int c = 0; c < 4; c++) b[c] = sv[(j0 + c) * 65 + d];
        #pragma unroll
        for (int r = 0; r < 4; r++)
            #pragma unroll
            for (int c = 0; c < 4; c++) acc[r][c] += a[r] * b[c];
    }

    __nv_bfloat16* mh = g_mh + (size_t)t * INNER;
    __nv_bfloat16* ml = g_ml + (size_t)t * INNER;
    #pragma unroll
    for (int r = 0; r < 4; r++) {
        const int i = i0 + r;
        const float rn_ = rnorm[i];
        __nv_bfloat16 h[4], l[4];
        #pragma unroll
        for (int c = 0; c < 4; c++) split_bf16(acc[r][c] * rn_, h[c], l[c]);
        __nv_bfloat162* ph = reinterpret_cast<__nv_bfloat162*>(mh + i * 64 + j0);
        __nv_bfloat162* pl = reinterpret_cast<__nv_bfloat162*>(ml + i * 64 + j0);
        ph[0] = __halves2bfloat162(h[0], h[1]); ph[1] = __halves2bfloat162(h[2], h[3]);
        pl[0] = __halves2bfloat162(l[0], l[1]); pl[1] = __halves2bfloat162(l[2], l[3]);
    }
}

// ---------------------------------------------------------------------------
extern "C" void kernel_launch(void* const* d_in, const int* in_sizes, int n_in,
                              void* d_out, int out_size)
{
    const float* x  = (const float*)d_in[0];
    const float* Wq = (const float*)d_in[1];
    const float* Wk = (const float*)d_in[2];
    const float* Wv = (const float*)d_in[3];
    const float* Wo = (const float*)d_in[4];
    const float* bo = (const float*)d_in[5];
    float* out = (float*)d_out;

    __nv_bfloat16 *xhi, *xlo, *wqh, *wql, *wkh, *wkl, *wvh, *wvl, *woh, *wol, *mh, *ml;
    float *qp, *kp, *vp;
    cudaGetSymbolAddress((void**)&xhi, g_xhi); cudaGetSymbolAddress((void**)&xlo, g_xlo);
    cudaGetSymbolAddress((void**)&wqh, g_wqh); cudaGetSymbolAddress((void**)&wql, g_wql);
    cudaGetSymbolAddress((void**)&wkh, g_wkh); cudaGetSymbolAddress((void**)&wkl, g_wkl);
    cudaGetSymbolAddress((void**)&wvh, g_wvh); cudaGetSymbolAddress((void**)&wvl, g_wvl);
    cudaGetSymbolAddress((void**)&woh, g_woh); cudaGetSymbolAddress((void**)&wol, g_wol);
    cudaGetSymbolAddress((void**)&mh,  g_mh);  cudaGetSymbolAddress((void**)&ml,  g_ml);
    cudaGetSymbolAddress((void**)&qp,  g_q);
    cudaGetSymbolAddress((void**)&kp,  g_k);
    cudaGetSymbolAddress((void**)&vp,  g_v);

    cudaFuncSetAttribute(gemm_split<0>, cudaFuncAttributeMaxDynamicSharedMemorySize, GEMM_SMEM);
    cudaFuncSetAttribute(gemm_split<1>, cudaFuncAttributeMaxDynamicSharedMemorySize, GEMM_SMEM);
    cudaFuncSetAttribute(gemm_split<2>, cudaFuncAttributeMaxDynamicSharedMemorySize, GEMM_SMEM);
    cudaFuncSetAttribute(gemm_split<3>, cudaFuncAttributeMaxDynamicSharedMemorySize, GEMM_SMEM);

    // Stage 0: hi/lo conversions
    split_fp32<<<(MTOK * DIM) / 1024, 256>>>(x, xhi, xlo, MTOK * DIM);
    dim3 tb(32, 8);
    transpose_split<<<dim3(INNER / 32, DIM / 32), tb>>>(Wq, wqh, wql, DIM, INNER);
    transpose_split<<<dim3(INNER / 32, DIM / 32), tb>>>(Wk, wkh, wkl, DIM, INNER);
    transpose_split<<<dim3(INNER / 32, DIM / 32), tb>>>(Wv, wvh, wvl, DIM, INNER);
    transpose_split<<<dim3(DIM / 32, INNER / 32), tb>>>(Wo, woh, wol, INNER, DIM);

    // Stage 1: QKV projections (HMMA split-bf16) with fused activations
    dim3 gQKV(INNER / BN, MTOK / BM);   // 16 x 64
    gemm_split<2><<<gQKV, 512, GEMM_SMEM>>>(xhi, xlo, wqh, wql, qp, nullptr, MTOK, INNER, DIM);
    gemm_split<1><<<gQKV, 512, GEMM_SMEM>>>(xhi, xlo, wkh, wkl, kp, nullptr, MTOK, INNER, DIM);
    gemm_split<0><<<gQKV, 512, GEMM_SMEM>>>(xhi, xlo, wvh, wvl, vp, nullptr, MTOK, INNER, DIM);

    // Stage 2: per-token collapsed attention (emits mid hi/lo)
    perf_mid_kernel<<<MTOK, 256>>>();

    // Stage 3: output projection + bias
    dim3 gOut(DIM / BN, MTOK / BM);     // 4 x 64
    gemm_split<3><<<gOut, 512, GEMM_SMEM>>>(mh, ml, woh, wol, out, bo, MTOK, DIM, INNER);
}

// round 14
// speedup vs baseline: 3.2479x; 1.0002x over previous
#include <cuda_runtime.h>
#include <cuda_bf16.h>
#include <cstdint>

// ---------------------------------------------------------------------------
// Problem constants
// ---------------------------------------------------------------------------
#define BATCH   2
#define SEQ     4096
#define DIM     1024
#define NHEADS  64
#define DHEAD   64
#define INNER   (NHEADS * DHEAD)     // 4096
#define MTOK    (BATCH * SEQ)        // 8192
#define SCALE_Q 0.125f
#define EPS     1e-6f

// ---------------------------------------------------------------------------
// Device scratch (static globals allowed; runtime allocation is not)
// ---------------------------------------------------------------------------
__device__ __align__(128) __nv_bfloat16 g_xhi[(size_t)MTOK * DIM];
__device__ __align__(128) __nv_bfloat16 g_xlo[(size_t)MTOK * DIM];
__device__ __align__(128) __nv_bfloat16 g_wqh[(size_t)INNER * DIM];   // [N][K]
__device__ __align__(128) __nv_bfloat16 g_wql[(size_t)INNER * DIM];
__device__ __align__(128) __nv_bfloat16 g_wkh[(size_t)INNER * DIM];
__device__ __align__(128) __nv_bfloat16 g_wkl[(size_t)INNER * DIM];
__device__ __align__(128) __nv_bfloat16 g_wvh[(size_t)INNER * DIM];
__device__ __align__(128) __nv_bfloat16 g_wvl[(size_t)INNER * DIM];
__device__ __align__(128) __nv_bfloat16 g_woh[(size_t)DIM * INNER];   // [1024][4096]
__device__ __align__(128) __nv_bfloat16 g_wol[(size_t)DIM * INNER];
__device__ __align__(128) float g_q[(size_t)MTOK * INNER];
__device__ __align__(128) float g_k[(size_t)MTOK * INNER];
__device__ __align__(128) float g_v[(size_t)MTOK * INNER];
__device__ __align__(128) __nv_bfloat16 g_mh[(size_t)MTOK * INNER];
__device__ __align__(128) __nv_bfloat16 g_ml[(size_t)MTOK * INNER];

// ---------------------------------------------------------------------------
// PTX helpers (plain sm_80+/sm_75+ — no 'a'-features; sm_103 target safe)
// ---------------------------------------------------------------------------
__device__ __forceinline__ uint32_t smem_u32(const void* p) {
    uint32_t a;
    asm("{ .reg .u64 t; cvta.to.shared.u64 t, %1; cvt.u32.u64 %0, t; }"
        : "=r"(a) : "l"(p));
    return a;
}

#define CP_ASYNC16(dst, src) \
    asm volatile("cp.async.cg.shared.global [%0], [%1], 16;" :: "r"(dst), "l"(src) : "memory")
#define CP_COMMIT() asm volatile("cp.async.commit_group;" ::: "memory")
#define CP_WAIT(n)  asm volatile("cp.async.wait_group %0;" :: "n"(n) : "memory")

#define LDSM4(r, addr) \
    asm volatile("ldmatrix.sync.aligned.m8n8.x4.shared.b16 {%0,%1,%2,%3}, [%4];" \
        : "=r"((r)[0]), "=r"((r)[1]), "=r"((r)[2]), "=r"((r)[3]) : "r"(addr))

__device__ __forceinline__ void mma16816(float* d, const uint32_t* a, const uint32_t* b) {
    asm volatile(
        "mma.sync.aligned.m16n8k16.row.col.f32.bf16.bf16.f32 "
        "{%0,%1,%2,%3}, {%4,%5,%6,%7}, {%8,%9}, {%0,%1,%2,%3};"
        : "+f"(d[0]), "+f"(d[1]), "+f"(d[2]), "+f"(d[3])
        : "r"(a[0]), "r"(a[1]), "r"(a[2]), "r"(a[3]), "r"(b[0]), "r"(b[1]));
}

__device__ __forceinline__ void split_bf16(float v, __nv_bfloat16& h, __nv_bfloat16& l) {
    h = __float2bfloat16_rn(v);
    l = __float2bfloat16_rn(v - __bfloat162float(h));
}

// ---------------------------------------------------------------------------
// Split-bf16 GEMM on HMMA (mma.sync):
//   C[M,N] fp32 = (Ahi+Alo)[M,K] @ (Bhi+Blo)[N,K]^T
// BM=128, BN=256, BK=64 (128B swizzled rows), 2-stage cp.async pipeline.
// 512 threads, 16 warps as 4(m) x 4(n); warp tile 32x64 (same micro-kernel
// as the R8 passing version).
// EPI: 0 identity, 1 relu, 2 relu*SCALE_Q, 3 +bias
// ---------------------------------------------------------------------------
#define BM 128
#define BN 256
#define BK 64
#define TILE_A_B (128 * 128)          // 16384 bytes (128 rows x 128B)
#define TILE_B_B (256 * 128)          // 32768 bytes (256 rows x 128B)
#define OFF_AHI 0
#define OFF_ALO (TILE_A_B)
#define OFF_BHI (2 * TILE_A_B)
#define OFF_BLO (2 * TILE_A_B + TILE_B_B)
#define STAGE_B (2 * TILE_A_B + 2 * TILE_B_B)   // 98304
#define GEMM_SMEM (2 * STAGE_B)                 // 196608

template<int EPI>
__global__ __launch_bounds__(512, 1)
void gemm_split(const __nv_bfloat16* __restrict__ Ahi, const __nv_bfloat16* __restrict__ Alo,
                const __nv_bfloat16* __restrict__ Bhi, const __nv_bfloat16* __restrict__ Blo,
                float* __restrict__ C, const float* __restrict__ bias,
                int M, int N, int K)
{
    extern __shared__ char smem[];
    const uint32_t sb = smem_u32(smem);
    const int tid  = threadIdx.x;
    const int wid  = tid >> 5;
    const int lane = tid & 31;
    const int bm = blockIdx.y * BM;
    const int bn = blockIdx.x * BN;
    const int wm = (wid & 3) * 32;    // warp m offset (4 groups over 128)
    const int wn = (wid >> 2) * 64;   // warp n offset (4 groups over 256)
    const int nchunk = K / BK;

    // Source row-base pointers per tile {Ahi, Alo, Bhi, Blo}
    const __nv_bfloat16* tsrc[4];
    tsrc[0] = Ahi + (size_t)bm * K;
    tsrc[1] = Alo + (size_t)bm * K;
    tsrc[2] = Bhi + (size_t)bn * K;
    tsrc[3] = Blo + (size_t)bn * K;

    // ---- async tile loader ----
    // 512 threads; granule = 16B (8 bf16). A tiles: 128 rows; B tiles: 256 rows.
    const int lg  = tid & 7;          // granule 0..7 within 128B row
    const int lr0 = tid >> 3;         // row 0..63 (+j*64)
    auto load_chunk = [&](int st, int c) {
        const uint32_t stbase = sb + st * STAGE_B;
        #pragma unroll
        for (int tile = 0; tile < 2; tile++) {       // A hi/lo: 128 rows each
            const uint32_t dbase = stbase + tile * TILE_A_B;
            const __nv_bfloat16* s = tsrc[tile] + (size_t)c * BK + lg * 8;
            #pragma unroll
            for (int j = 0; j < 2; j++) {
                const int r = lr0 + j * 64;
                CP_ASYNC16(dbase + r * 128 + ((lg ^ (r & 7)) << 4),
                           s + (size_t)r * K);
            }
        }
        #pragma unroll
        for (int tile = 2; tile < 4; tile++) {       // B hi/lo: 256 rows each
            const uint32_t dbase = stbase + OFF_BHI + (tile - 2) * TILE_B_B;
            const __nv_bfloat16* s = tsrc[tile] + (size_t)c * BK + lg * 8;
            #pragma unroll
            for (int j = 0; j < 4; j++) {
                const int r = lr0 + j * 64;
                CP_ASYNC16(dbase + r * 128 + ((lg ^ (r & 7)) << 4),
                           s + (size_t)r * K);
            }
        }
        CP_COMMIT();
    };

    float acc[2][8][4];
    #pragma unroll
    for (int mi = 0; mi < 2; mi++)
        #pragma unroll
        for (int ni = 0; ni < 8; ni++)
            #pragma unroll
            for (int v = 0; v < 4; v++) acc[mi][ni][v] = 0.f;

    load_chunk(0, 0);

    // ldmatrix lane addressing (constant per thread, within a k-step)
    const int a_row = wm + (lane & 15);                      // + mi*16
    const int a_kg  = lane >> 4;                             // +2*kk
    const int b_row = wn + (lane & 7) + ((lane >> 4) << 3);  // + p*16
    const int b_kg  = (lane >> 3) & 1;                       // +2*kk

    for (int c = 0; c < nchunk; c++) {
        if (c + 1 < nchunk) { load_chunk((c + 1) & 1, c + 1); CP_WAIT(1); }
        else                { CP_WAIT(0); }
        __syncthreads();

        const uint32_t stb  = sb + (c & 1) * STAGE_B;
        const uint32_t sA_hi = stb + OFF_AHI;
        const uint32_t sA_lo = stb + OFF_ALO;
        const uint32_t sB_hi = stb + OFF_BHI;
        const uint32_t sB_lo = stb + OFF_BLO;

        #pragma unroll
        for (int kk = 0; kk < 4; kk++) {           // 4 x k16 per chunk
            uint32_t ahi[2][4], alo[2][4];
            #pragma unroll
            for (int mi = 0; mi < 2; mi++) {
                const int r = a_row + mi * 16;
                const int kg = 2 * kk + a_kg;
                const uint32_t off = r * 128 + ((kg ^ (r & 7)) << 4);
                LDSM4(ahi[mi], sA_hi + off);
                LDSM4(alo[mi], sA_lo + off);
            }
            uint32_t bhi[8][2], blo[8][2];
            #pragma unroll
            for (int p = 0; p < 4; p++) {          // pair of n8 tiles per x4
                const int r = b_row + p * 16;
                const int kg = 2 * kk + b_kg;
                const uint32_t off = r * 128 + ((kg ^ (r & 7)) << 4);
                uint32_t t[4];
                LDSM4(t, sB_hi + off);
                bhi[p * 2][0] = t[0]; bhi[p * 2][1] = t[1];
                bhi[p * 2 + 1][0] = t[2]; bhi[p * 2 + 1][1] = t[3];
                LDSM4(t, sB_lo + off);
                blo[p * 2][0] = t[0]; blo[p * 2][1] = t[1];
                blo[p * 2 + 1][0] = t[2]; blo[p * 2 + 1][1] = t[3];
            }
            #pragma unroll
            for (int mi = 0; mi < 2; mi++)
                #pragma unroll
                for (int ni = 0; ni < 8; ni++) {
                    mma16816(acc[mi][ni], ahi[mi], bhi[ni]);  // hi*hi
                    mma16816(acc[mi][ni], ahi[mi], blo[ni]);  // hi*lo
                    mma16816(acc[mi][ni], alo[mi], bhi[ni]);  // lo*hi
                }
        }
        __syncthreads();
    }

    // ---- epilogue ----
    const int erow  = bm + wm + (lane >> 2);
    const int ecol0 = bn + wn + (lane & 3) * 2;
    #pragma unroll
    for (int mi = 0; mi < 2; mi++) {
        #pragma unroll
        for (int ni = 0; ni < 8; ni++) {
            const int row = erow + mi * 16;
            const int col = ecol0 + ni * 8;
            float v[4] = { acc[mi][ni][0], acc[mi][ni][1],
                           acc[mi][ni][2], acc[mi][ni][3] };
            if (EPI == 1) {
                #pragma unroll
                for (int q = 0; q < 4; q++) v[q] = fmaxf(v[q], 0.f);
            }
            if (EPI == 2) {
                #pragma unroll
                for (int q = 0; q < 4; q++) v[q] = fmaxf(v[q], 0.f) * SCALE_Q;
            }
            if (EPI == 3) {
                const float b0 = __ldg(&bias[col]), b1 = __ldg(&bias[col + 1]);
                v[0] += b0; v[1] += b1; v[2] += b0; v[3] += b1;
            }
            *reinterpret_cast<float2*>(C + (size_t)row * N + col) =
                make_float2(v[0], v[1]);
            *reinterpret_cast<float2*>(C + (size_t)(row + 8) * N + col) =
                make_float2(v[2], v[3]);
        }
    }
}

// ---------------------------------------------------------------------------
// Conversion kernels
// ---------------------------------------------------------------------------
__global__ __launch_bounds__(256)
void split_fp32(const float* __restrict__ in, __nv_bfloat16* __restrict__ hi,
                __nv_bfloat16* __restrict__ lo, int n)
{
    const int i = (blockIdx.x * 256 + threadIdx.x) * 4;
    if (i >= n) return;
    const float4 v = *reinterpret_cast<const float4*>(in + i);
    __nv_bfloat16 h0, h1, h2, h3, l0, l1, l2, l3;
    split_bf16(v.x, h0, l0); split_bf16(v.y, h1, l1);
    split_bf16(v.z, h2, l2); split_bf16(v.w, h3, l3);
    __nv_bfloat162* ph = reinterpret_cast<__nv_bfloat162*>(hi + i);
    __nv_bfloat162* pl = reinterpret_cast<__nv_bfloat162*>(lo + i);
    ph[0] = __halves2bfloat162(h0, h1); ph[1] = __halves2bfloat162(h2, h3);
    pl[0] = __halves2bfloat162(l0, l1); pl[1] = __halves2bfloat162(l2, l3);
}

// W[K][N] fp32 -> T_hi/T_lo[N][K] bf16 (transpose + split)
__global__ __launch_bounds__(256)
void transpose_split(const float* __restrict__ W, __nv_bfloat16* __restrict__ Th,
                     __nv_bfloat16* __restrict__ Tl, int K, int N)
{
    __shared__ float tile[32][33];
    const int n0 = blockIdx.x * 32, k0 = blockIdx.y * 32;
    const int tx = threadIdx.x, ty = threadIdx.y;
    #pragma unroll
    for (int j = 0; j < 4; j++)
        tile[ty + j * 8][tx] = W[(size_t)(k0 + ty + j * 8) * N + n0 + tx];
    __syncthreads();
    #pragma unroll
    for (int j = 0; j < 4; j++) {
        const int n = n0 + ty + j * 8, k = k0 + tx;
        __nv_bfloat16 h, l;
        split_bf16(tile[tx][ty + j * 8], h, l);
        Th[(size_t)n * K + k] = h;
        Tl[(size_t)n * K + k] = l;
    }
}

// ---------------------------------------------------------------------------
// Per-token stage, 4x4 register-blocked; emits bf16 hi/lo directly.
//   w[d] = sum_i k[i,d];  qw = q*w;  norm[i] = sum_d qw[i,d]
//   mid[i,j] = sum_d qw[i,d]*v[j,d] / (norm[i]+eps)
// ---------------------------------------------------------------------------
__global__ __launch_bounds__(256)
void perf_mid_kernel()
{
    __shared__ float sq[64 * 65];
    __shared__ float sv[64 * 65];
    __shared__ float w[64];
    __shared__ float rnorm[64];

    const int t   = blockIdx.x;
    const int tid = threadIdx.x;
    const float* qt = g_q + (size_t)t * INNER;
    const float* kt = g_k + (size_t)t * INNER;
    const float* vt = g_v + (size_t)t * INNER;

    for (int idx = tid; idx < 4096; idx += 256) {
        const int i = idx >> 6, d = idx & 63;
        sq[i * 65 + d] = qt[idx];
        sv[i * 65 + d] = vt[idx];
    }
    if (tid < 64) {
        float s = 0.f;
        #pragma unroll 8
        for (int i = 0; i < 64; i++) s += kt[i * 64 + tid];
        w[tid] = s;
    }
    __syncthreads();

    for (int idx = tid; idx < 4096; idx += 256) {
        const int i = idx >> 6, d = idx & 63;
        sq[i * 65 + d] *= w[d];
    }
    __syncthreads();

    if (tid < 64) {
        float s = 0.f;
        #pragma unroll 8
        for (int d = 0; d < 64; d++) s += sq[tid * 65 + d];
        rnorm[tid] = 1.f / (s + EPS);
    }
    __syncthreads();

    const int ti = tid >> 4, tj = tid & 15;
    const int i0 = ti * 4, j0 = tj * 4;
    float acc[4][4];
    #pragma unroll
    for (int r = 0; r < 4; r++)
        #pragma unroll
        for (int c = 0; c < 4; c++) acc[r][c] = 0.f;

    #pragma unroll 4
    for (int d = 0; d < 64; d++) {
        float a[4], b[4];
        #pragma unroll
        for (int r = 0; r < 4; r++) a[r] = sq[(i0 + r) * 65 + d];
        #pragma unroll
        for (int c = 0; c < 4; c++) b[c] = sv[(j0 + c) * 65 + d];
        #pragma unroll
        for (int r = 0; r < 4; r++)
            #pragma unroll
            for (int c = 0; c < 4; c++) acc[r][c] += a[r] * b[c];
    }

    __nv_bfloat16* mh = g_mh + (size_t)t * INNER;
    __nv_bfloat16* ml = g_ml + (size_t)t * INNER;
    #pragma unroll
    for (int r = 0; r < 4; r++) {
        const int i = i0 + r;
        const float rn_ = rnorm[i];
        __nv_bfloat16 h[4], l[4];
        #pragma unroll
        for (int c = 0; c < 4; c++) split_bf16(acc[r][c] * rn_, h[c], l[c]);
        __nv_bfloat162* ph = reinterpret_cast<__nv_bfloat162*>(mh + i * 64 + j0);
        __nv_bfloat162* pl = reinterpret_cast<__nv_bfloat162*>(ml + i * 64 + j0);
        ph[0] = __halves2bfloat162(h[0], h[1]); ph[1] = __halves2bfloat162(h[2], h[3]);
        pl[0] = __halves2bfloat162(l[0], l[1]); pl[1] = __halves2bfloat162(l[2], l[3]);
    }
}

// ---------------------------------------------------------------------------
extern "C" void kernel_launch(void* const* d_in, const int* in_sizes, int n_in,
                              void* d_out, int out_size)
{
    const float* x  = (const float*)d_in[0];
    const float* Wq = (const float*)d_in[1];
    const float* Wk = (const float*)d_in[2];
    const float* Wv = (const float*)d_in[3];
    const float* Wo = (const float*)d_in[4];
    const float* bo = (const float*)d_in[5];
    float* out = (float*)d_out;

    __nv_bfloat16 *xhi, *xlo, *wqh, *wql, *wkh, *wkl, *wvh, *wvl, *woh, *wol, *mh, *ml;
    float *qp, *kp, *vp;
    cudaGetSymbolAddress((void**)&xhi, g_xhi); cudaGetSymbolAddress((void**)&xlo, g_xlo);
    cudaGetSymbolAddress((void**)&wqh, g_wqh); cudaGetSymbolAddress((void**)&wql, g_wql);
    cudaGetSymbolAddress((void**)&wkh, g_wkh); cudaGetSymbolAddress((void**)&wkl, g_wkl);
    cudaGetSymbolAddress((void**)&wvh, g_wvh); cudaGetSymbolAddress((void**)&wvl, g_wvl);
    cudaGetSymbolAddress((void**)&woh, g_woh); cudaGetSymbolAddress((void**)&wol, g_wol);
    cudaGetSymbolAddress((void**)&mh,  g_mh);  cudaGetSymbolAddress((void**)&ml,  g_ml);
    cudaGetSymbolAddress((void**)&qp,  g_q);
    cudaGetSymbolAddress((void**)&kp,  g_k);
    cudaGetSymbolAddress((void**)&vp,  g_v);

    cudaFuncSetAttribute(gemm_split<0>, cudaFuncAttributeMaxDynamicSharedMemorySize, GEMM_SMEM);
    cudaFuncSetAttribute(gemm_split<1>, cudaFuncAttributeMaxDynamicSharedMemorySize, GEMM_SMEM);
    cudaFuncSetAttribute(gemm_split<2>, cudaFuncAttributeMaxDynamicSharedMemorySize, GEMM_SMEM);
    cudaFuncSetAttribute(gemm_split<3>, cudaFuncAttributeMaxDynamicSharedMemorySize, GEMM_SMEM);

    // Stage 0: hi/lo conversions
    split_fp32<<<(MTOK * DIM) / 1024, 256>>>(x, xhi, xlo, MTOK * DIM);
    dim3 tb(32, 8);
    transpose_split<<<dim3(INNER / 32, DIM / 32), tb>>>(Wq, wqh, wql, DIM, INNER);
    transpose_split<<<dim3(INNER / 32, DIM / 32), tb>>>(Wk, wkh, wkl, DIM, INNER);
    transpose_split<<<dim3(INNER / 32, DIM / 32), tb>>>(Wv, wvh, wvl, DIM, INNER);
    transpose_split<<<dim3(DIM / 32, INNER / 32), tb>>>(Wo, woh, wol, INNER, DIM);

    // Stage 1: QKV projections (HMMA split-bf16) with fused activations
    dim3 gQKV(INNER / BN, MTOK / BM);   // 16 x 64
    gemm_split<2><<<gQKV, 512, GEMM_SMEM>>>(xhi, xlo, wqh, wql, qp, nullptr, MTOK, INNER, DIM);
    gemm_split<1><<<gQKV, 512, GEMM_SMEM>>>(xhi, xlo, wkh, wkl, kp, nullptr, MTOK, INNER, DIM);
    gemm_split<0><<<gQKV, 512, GEMM_SMEM>>>(xhi, xlo, wvh, wvl, vp, nullptr, MTOK, INNER, DIM);

    // Stage 2: per-token collapsed attention (emits mid hi/lo)
    perf_mid_kernel<<<MTOK, 256>>>();

    // Stage 3: output projection + bias
    dim3 gOut(DIM / BN, MTOK / BM);     // 4 x 64
    gemm_split<3><<<gOut, 512, GEMM_SMEM>>>(mh, ml, woh, wol, out, bo, MTOK, DIM, INNER);
}

// round 15
// speedup vs baseline: 6.8894x; 2.1212x over previous
#include <cuda_runtime.h>
#include <cuda_fp16.h>
#include <cstdint>

// ---------------------------------------------------------------------------
// Problem constants
// ---------------------------------------------------------------------------
#define BATCH   2
#define SEQ     4096
#define DIM     1024
#define NHEADS  64
#define DHEAD   64
#define INNER   (NHEADS * DHEAD)     // 4096
#define MTOK    (BATCH * SEQ)        // 8192
#define SCALE_Q 0.125f
#define EPS     1e-6f

// ---------------------------------------------------------------------------
// Device scratch (static globals allowed; runtime allocation is not)
// ---------------------------------------------------------------------------
__device__ __align__(128) __half g_xh[(size_t)MTOK * DIM];
__device__ __align__(128) __half g_wq[(size_t)INNER * DIM];   // [N][K]
__device__ __align__(128) __half g_wk[(size_t)INNER * DIM];
__device__ __align__(128) __half g_wv[(size_t)INNER * DIM];
__device__ __align__(128) __half g_wo[(size_t)DIM * INNER];   // [1024][4096]
__device__ __align__(128) float g_q[(size_t)MTOK * INNER];
__device__ __align__(128) float g_k[(size_t)MTOK * INNER];
__device__ __align__(128) float g_v[(size_t)MTOK * INNER];
__device__ __align__(128) __half g_m[(size_t)MTOK * INNER];

// ---------------------------------------------------------------------------
// PTX helpers (plain sm_80+/sm_75+ — no 'a'-features; sm_103 target safe)
// ---------------------------------------------------------------------------
__device__ __forceinline__ uint32_t smem_u32(const void* p) {
    uint32_t a;
    asm("{ .reg .u64 t; cvta.to.shared.u64 t, %1; cvt.u32.u64 %0, t; }"
        : "=r"(a) : "l"(p));
    return a;
}

#define CP_ASYNC16(dst, src) \
    asm volatile("cp.async.cg.shared.global [%0], [%1], 16;" :: "r"(dst), "l"(src) : "memory")
#define CP_COMMIT() asm volatile("cp.async.commit_group;" ::: "memory")
#define CP_WAIT(n)  asm volatile("cp.async.wait_group %0;" :: "n"(n) : "memory")

#define LDSM4(r, addr) \
    asm volatile("ldmatrix.sync.aligned.m8n8.x4.shared.b16 {%0,%1,%2,%3}, [%4];" \
        : "=r"((r)[0]), "=r"((r)[1]), "=r"((r)[2]), "=r"((r)[3]) : "r"(addr))

__device__ __forceinline__ void mma16816(float* d, const uint32_t* a, const uint32_t* b) {
    asm volatile(
        "mma.sync.aligned.m16n8k16.row.col.f32.f16.f16.f32 "
        "{%0,%1,%2,%3}, {%4,%5,%6,%7}, {%8,%9}, {%0,%1,%2,%3};"
        : "+f"(d[0]), "+f"(d[1]), "+f"(d[2]), "+f"(d[3])
        : "r"(a[0]), "r"(a[1]), "r"(a[2]), "r"(a[3]), "r"(b[0]), "r"(b[1]));
}

// ---------------------------------------------------------------------------
// fp16 GEMM on HMMA (mma.sync):  C[M,N] fp32 = A[M,K] @ B[N,K]^T
// BM=128, BN=256, BK=64 (128B swizzled rows), 3-stage cp.async pipeline.
// 512 threads, 16 warps as 4(m) x 4(n); warp tile 32x64.
// EPI: 0 identity, 1 relu, 2 relu*SCALE_Q, 3 +bias
// ---------------------------------------------------------------------------
#define BM 128
#define BN 256
#define BK 64
#define TILE_A_B (128 * 128)          // 16384 bytes (128 rows x 128B)
#define TILE_B_B (256 * 128)          // 32768 bytes (256 rows x 128B)
#define OFF_A 0
#define OFF_B (TILE_A_B)
#define STAGE_B (TILE_A_B + TILE_B_B)           // 49152
#define NSTAGE 3
#define GEMM_SMEM (NSTAGE * STAGE_B)            // 147456

template<int EPI>
__global__ __launch_bounds__(512, 1)
void gemm_fp16(const __half* __restrict__ A, const __half* __restrict__ B,
               float* __restrict__ C, const float* __restrict__ bias,
               int M, int N, int K)
{
    extern __shared__ char smem[];
    const uint32_t sb = smem_u32(smem);
    const int tid  = threadIdx.x;
    const int wid  = tid >> 5;
    const int lane = tid & 31;
    const int bm = blockIdx.y * BM;
    const int bn = blockIdx.x * BN;
    const int wm = (wid & 3) * 32;    // warp m offset (4 groups over 128)
    const int wn = (wid >> 2) * 64;   // warp n offset (4 groups over 256)
    const int nchunk = K / BK;

    const __half* Abase = A + (size_t)bm * K;
    const __half* Bbase = B + (size_t)bn * K;

    // ---- async tile loader ----
    // 512 threads; granule = 16B (8 halves). A: 128 rows; B: 256 rows.
    const int lg  = tid & 7;          // granule 0..7 within 128B row
    const int lr0 = tid >> 3;         // row 0..63 (+j*64)
    auto load_chunk = [&](int st, int c) {
        const uint32_t stbase = sb + st * STAGE_B;
        {
            const uint32_t dbase = stbase + OFF_A;
            const __half* s = Abase + (size_t)c * BK + lg * 8;
            #pragma unroll
            for (int j = 0; j < 2; j++) {
                const int r = lr0 + j * 64;
                CP_ASYNC16(dbase + r * 128 + ((lg ^ (r & 7)) << 4),
                           s + (size_t)r * K);
            }
        }
        {
            const uint32_t dbase = stbase + OFF_B;
            const __half* s = Bbase + (size_t)c * BK + lg * 8;
            #pragma unroll
            for (int j = 0; j < 4; j++) {
                const int r = lr0 + j * 64;
                CP_ASYNC16(dbase + r * 128 + ((lg ^ (r & 7)) << 4),
                           s + (size_t)r * K);
            }
        }
        CP_COMMIT();
    };

    float acc[2][8][4];
    #pragma unroll
    for (int mi = 0; mi < 2; mi++)
        #pragma unroll
        for (int ni = 0; ni < 8; ni++)
            #pragma unroll
            for (int v = 0; v < 4; v++) acc[mi][ni][v] = 0.f;

    load_chunk(0, 0);
    load_chunk(1, 1);

    // ldmatrix lane addressing (constant per thread, within a k-step)
    const int a_row = wm + (lane & 15);                      // + mi*16
    const int a_kg  = lane >> 4;                             // +2*kk
    const int b_row = wn + (lane & 7) + ((lane >> 4) << 3);  // + p*16
    const int b_kg  = (lane >> 3) & 1;                       // +2*kk

    int st = 0;
    for (int c = 0; c < nchunk; c++) {
        if (c + 1 < nchunk) { CP_WAIT(1); } else { CP_WAIT(0); }
        __syncthreads();
        // prefetch chunk c+2 into the buffer freed by chunk c-1
        if (c + 2 < nchunk) {
            int st2 = st + 2; if (st2 >= NSTAGE) st2 -= NSTAGE;
            load_chunk(st2, c + 2);
        }

        const uint32_t stb = sb + st * STAGE_B;
        const uint32_t sA  = stb + OFF_A;
        const uint32_t sB  = stb + OFF_B;

        #pragma unroll
        for (int kk = 0; kk < 4; kk++) {           // 4 x k16 per chunk
            uint32_t av[2][4];
            #pragma unroll
            for (int mi = 0; mi < 2; mi++) {
                const int r = a_row + mi * 16;
                const int kg = 2 * kk + a_kg;
                LDSM4(av[mi], sA + r * 128 + ((kg ^ (r & 7)) << 4));
            }
            uint32_t bv[8][2];
            #pragma unroll
            for (int p = 0; p < 4; p++) {          // pair of n8 tiles per x4
                const int r = b_row + p * 16;
                const int kg = 2 * kk + b_kg;
                uint32_t t[4];
                LDSM4(t, sB + r * 128 + ((kg ^ (r & 7)) << 4));
                bv[p * 2][0] = t[0]; bv[p * 2][1] = t[1];
                bv[p * 2 + 1][0] = t[2]; bv[p * 2 + 1][1] = t[3];
            }
            #pragma unroll
            for (int mi = 0; mi < 2; mi++)
                #pragma unroll
                for (int ni = 0; ni < 8; ni++)
                    mma16816(acc[mi][ni], av[mi], bv[ni]);
        }
        st++; if (st >= NSTAGE) st = 0;
    }

    // ---- epilogue ----
    const int erow  = bm + wm + (lane >> 2);
    const int ecol0 = bn + wn + (lane & 3) * 2;
    #pragma unroll
    for (int mi = 0; mi < 2; mi++) {
        #pragma unroll
        for (int ni = 0; ni < 8; ni++) {
            const int row = erow + mi * 16;
            const int col = ecol0 + ni * 8;
            float v[4] = { acc[mi][ni][0], acc[mi][ni][1],
                           acc[mi][ni][2], acc[mi][ni][3] };
            if (EPI == 1) {
                #pragma unroll
                for (int q = 0; q < 4; q++) v[q] = fmaxf(v[q], 0.f);
            }
            if (EPI == 2) {
                #pragma unroll
                for (int q = 0; q < 4; q++) v[q] = fmaxf(v[q], 0.f) * SCALE_Q;
            }
            if (EPI == 3) {
                const float b0 = __ldg(&bias[col]), b1 = __ldg(&bias[col + 1]);
                v[0] += b0; v[1] += b1; v[2] += b0; v[3] += b1;
            }
            *reinterpret_cast<float2*>(C + (size_t)row * N + col) =
                make_float2(v[0], v[1]);
            *reinterpret_cast<float2*>(C + (size_t)(row + 8) * N + col) =
                make_float2(v[2], v[3]);
        }
    }
}

// ---------------------------------------------------------------------------
// Conversion kernels
// ---------------------------------------------------------------------------
__global__ __launch_bounds__(256)
void cvt_fp16(const float* __restrict__ in, __half* __restrict__ out, int n)
{
    const int i = (blockIdx.x * 256 + threadIdx.x) * 4;
    if (i >= n) return;
    const float4 v = *reinterpret_cast<const float4*>(in + i);
    __half2* po = reinterpret_cast<__half2*>(out + i);
    po[0] = __floats2half2_rn(v.x, v.y);
    po[1] = __floats2half2_rn(v.z, v.w);
}

// W[K][N] fp32 -> T[N][K] fp16 (transpose + convert)
__global__ __launch_bounds__(256)
void transpose_cvt(const float* __restrict__ W, __half* __restrict__ T,
                   int K, int N)
{
    __shared__ float tile[32][33];
    const int n0 = blockIdx.x * 32, k0 = blockIdx.y * 32;
    const int tx = threadIdx.x, ty = threadIdx.y;
    #pragma unroll
    for (int j = 0; j < 4; j++)
        tile[ty + j * 8][tx] = W[(size_t)(k0 + ty + j * 8) * N + n0 + tx];
    __syncthreads();
    #pragma unroll
    for (int j = 0; j < 4; j++) {
        const int n = n0 + ty + j * 8, k = k0 + tx;
        T[(size_t)n * K + k] = __float2half_rn(tile[tx][ty + j * 8]);
    }
}

// ---------------------------------------------------------------------------
// Per-token stage, 4x4 register-blocked; emits fp16 directly.
//   w[d] = sum_i k[i,d];  qw = q*w;  norm[i] = sum_d qw[i,d]
//   mid[i,j] = sum_d qw[i,d]*v[j,d] / (norm[i]+eps)
// ---------------------------------------------------------------------------
__global__ __launch_bounds__(256)
void perf_mid_kernel()
{
    __shared__ float sq[64 * 65];
    __shared__ float sv[64 * 65];
    __shared__ float w[64];
    __shared__ float rnorm[64];

    const int t   = blockIdx.x;
    const int tid = threadIdx.x;
    const float* qt = g_q + (size_t)t * INNER;
    const float* kt = g_k + (size_t)t * INNER;
    const float* vt = g_v + (size_t)t * INNER;

    for (int idx = tid; idx < 4096; idx += 256) {
        const int i = idx >> 6, d = idx & 63;
        sq[i * 65 + d] = qt[idx];
        sv[i * 65 + d] = vt[idx];
    }
    if (tid < 64) {
        float s = 0.f;
        #pragma unroll 8
        for (int i = 0; i < 64; i++) s += kt[i * 64 + tid];
        w[tid] = s;
    }
    __syncthreads();

    for (int idx = tid; idx < 4096; idx += 256) {
        const int i = idx >> 6, d = idx & 63;
        sq[i * 65 + d] *= w[d];
    }
    __syncthreads();

    if (tid < 64) {
        float s = 0.f;
        #pragma unroll 8
        for (int d = 0; d < 64; d++) s += sq[tid * 65 + d];
        rnorm[tid] = 1.f / (s + EPS);
    }
    __syncthreads();

    const int ti = tid >> 4, tj = tid & 15;
    const int i0 = ti * 4, j0 = tj * 4;
    float acc[4][4];
    #pragma unroll
    for (int r = 0; r < 4; r++)
        #pragma unroll
        for (int c = 0; c < 4; c++) acc[r][c] = 0.f;

    #pragma unroll 4
    for (int d = 0; d < 64; d++) {
        float a[4], b[4];
        #pragma unroll
        for (int r = 0; r < 4; r++) a[r] = sq[(i0 + r) * 65 + d];
        #pragma unroll
        for (int c = 0; c < 4; c++) b[c] = sv[(j0 + c) * 65 + d];
        #pragma unroll
        for (int r = 0; r < 4; r++)
            #pragma unroll
            for (int c = 0; c < 4; c++) acc[r][c] += a[r] * b[c];
    }

    __half* mo = g_m + (size_t)t * INNER;
    #pragma unroll
    for (int r = 0; r < 4; r++) {
        const int i = i0 + r;
        const float rn_ = rnorm[i];
        __half2* po = reinterpret_cast<__half2*>(mo + i * 64 + j0);
        po[0] = __floats2half2_rn(acc[r][0] * rn_, acc[r][1] * rn_);
        po[1] = __floats2half2_rn(acc[r][2] * rn_, acc[r][3] * rn_);
    }
}

// ---------------------------------------------------------------------------
extern "C" void kernel_launch(void* const* d_in, const int* in_sizes, int n_in,
                              void* d_out, int out_size)
{
    const float* x  = (const float*)d_in[0];
    const float* Wq = (const float*)d_in[1];
    const float* Wk = (const float*)d_in[2];
    const float* Wv = (const float*)d_in[3];
    const float* Wo = (const float*)d_in[4];
    const float* bo = (const float*)d_in[5];
    float* out = (float*)d_out;

    __half *xh, *wq, *wk, *wv, *wo, *mp;
    float *qp, *kp, *vp;
    cudaGetSymbolAddress((void**)&xh, g_xh);
    cudaGetSymbolAddress((void**)&wq, g_wq);
    cudaGetSymbolAddress((void**)&wk, g_wk);
    cudaGetSymbolAddress((void**)&wv, g_wv);
    cudaGetSymbolAddress((void**)&wo, g_wo);
    cudaGetSymbolAddress((void**)&mp, g_m);
    cudaGetSymbolAddress((void**)&qp, g_q);
    cudaGetSymbolAddress((void**)&kp, g_k);
    cudaGetSymbolAddress((void**)&vp, g_v);

    cudaFuncSetAttribute(gemm_fp16<0>, cudaFuncAttributeMaxDynamicSharedMemorySize, GEMM_SMEM);
    cudaFuncSetAttribute(gemm_fp16<1>, cudaFuncAttributeMaxDynamicSharedMemorySize, GEMM_SMEM);
    cudaFuncSetAttribute(gemm_fp16<2>, cudaFuncAttributeMaxDynamicSharedMemorySize, GEMM_SMEM);
    cudaFuncSetAttribute(gemm_fp16<3>, cudaFuncAttributeMaxDynamicSharedMemorySize, GEMM_SMEM);

    // Stage 0: fp16 conversions
    cvt_fp16<<<(MTOK * DIM) / 1024, 256>>>(x, xh, MTOK * DIM);
    dim3 tb(32, 8);
    transpose_cvt<<<dim3(INNER / 32, DIM / 32), tb>>>(Wq, wq, DIM, INNER);
    transpose_cvt<<<dim3(INNER / 32, DIM / 32), tb>>>(Wk, wk, DIM, INNER);
    transpose_cvt<<<dim3(INNER / 32, DIM / 32), tb>>>(Wv, wv, DIM, INNER);
    transpose_cvt<<<dim3(DIM / 32, INNER / 32), tb>>>(Wo, wo, INNER, DIM);

    // Stage 1: QKV projections (HMMA fp16) with fused activations
    dim3 gQKV(INNER / BN, MTOK / BM);   // 16 x 64
    gemm_fp16<2><<<gQKV, 512, GEMM_SMEM>>>(xh, wq, qp, nullptr, MTOK, INNER, DIM);
    gemm_fp16<1><<<gQKV, 512, GEMM_SMEM>>>(xh, wk, kp, nullptr, MTOK, INNER, DIM);
    gemm_fp16<0><<<gQKV, 512, GEMM_SMEM>>>(xh, wv, vp, nullptr, MTOK, INNER, DIM);

    // Stage 2: per-token collapsed attention (emits fp16 mid)
    perf_mid_kernel<<<MTOK, 256>>>();

    // Stage 3: output projection + bias
    dim3 gOut(DIM / BN, MTOK / BM);     // 4 x 64
    gemm_fp16<3><<<gOut, 512, GEMM_SMEM>>>(mp, wo, out, bo, MTOK, DIM, INNER);
}

// round 16
// speedup vs baseline: 6.9266x; 1.0054x over previous
#include <cuda_runtime.h>
#include <cuda_fp16.h>
#include <cstdint>

// ---------------------------------------------------------------------------
// Problem constants
// ---------------------------------------------------------------------------
#define BATCH   2
#define SEQ     4096
#define DIM     1024
#define NHEADS  64
#define DHEAD   64
#define INNER   (NHEADS * DHEAD)     // 4096
#define MTOK    (BATCH * SEQ)        // 8192
#define SCALE_Q 0.125f
#define EPS     1e-6f

// ---------------------------------------------------------------------------
// Device scratch (static globals allowed; runtime allocation is not)
// ---------------------------------------------------------------------------
__device__ __align__(128) __half g_xh[(size_t)MTOK * DIM];
__device__ __align__(128) __half g_wq[(size_t)INNER * DIM];   // [N][K]
__device__ __align__(128) __half g_wk[(size_t)INNER * DIM];
__device__ __align__(128) __half g_wv[(size_t)INNER * DIM];
__device__ __align__(128) __half g_wo[(size_t)DIM * INNER];   // [1024][4096]
__device__ __align__(128) float g_q[(size_t)MTOK * INNER];
__device__ __align__(128) float g_k[(size_t)MTOK * INNER];
__device__ __align__(128) float g_v[(size_t)MTOK * INNER];
__device__ __align__(128) __half g_m[(size_t)MTOK * INNER];

// ---------------------------------------------------------------------------
// PTX helpers (plain sm_80+/sm_75+ — no 'a'-features; sm_103 target safe)
// ---------------------------------------------------------------------------
__device__ __forceinline__ uint32_t smem_u32(const void* p) {
    uint32_t a;
    asm("{ .reg .u64 t; cvta.to.shared.u64 t, %1; cvt.u32.u64 %0, t; }"
        : "=r"(a) : "l"(p));
    return a;
}

#define CP_ASYNC16(dst, src) \
    asm volatile("cp.async.cg.shared.global [%0], [%1], 16;" :: "r"(dst), "l"(src) : "memory")
#define CP_COMMIT() asm volatile("cp.async.commit_group;" ::: "memory")
#define CP_WAIT(n)  asm volatile("cp.async.wait_group %0;" :: "n"(n) : "memory")

#define LDSM4(r, addr) \
    asm volatile("ldmatrix.sync.aligned.m8n8.x4.shared.b16 {%0,%1,%2,%3}, [%4];" \
        : "=r"((r)[0]), "=r"((r)[1]), "=r"((r)[2]), "=r"((r)[3]) : "r"(addr))

__device__ __forceinline__ void mma16816(float* d, const uint32_t* a, const uint32_t* b) {
    asm volatile(
        "mma.sync.aligned.m16n8k16.row.col.f32.f16.f16.f32 "
        "{%0,%1,%2,%3}, {%4,%5,%6,%7}, {%8,%9}, {%0,%1,%2,%3};"
        : "+f"(d[0]), "+f"(d[1]), "+f"(d[2]), "+f"(d[3])
        : "r"(a[0]), "r"(a[1]), "r"(a[2]), "r"(a[3]), "r"(b[0]), "r"(b[1]));
}

// ---------------------------------------------------------------------------
// fp16 GEMM on HMMA (mma.sync):  C[M,N] fp32 = A[M,K] @ B[N,K]^T
// BM=128, BN=256, BK=64 (128B swizzled rows), 3-stage cp.async pipeline.
// 512 threads, 16 warps as 4(m) x 4(n); warp tile 32x64.
// EPI: 0 identity, 1 relu, 2 relu*SCALE_Q, 3 +bias
// ---------------------------------------------------------------------------
#define BM 128
#define BN 256
#define BK 64
#define TILE_A_B (128 * 128)          // 16384 bytes (128 rows x 128B)
#define TILE_B_B (256 * 128)          // 32768 bytes (256 rows x 128B)
#define OFF_A 0
#define OFF_B (TILE_A_B)
#define STAGE_B (TILE_A_B + TILE_B_B)           // 49152
#define NSTAGE 3
#define GEMM_SMEM (NSTAGE * STAGE_B)            // 147456

template<int EPI>
__global__ __launch_bounds__(512, 1)
void gemm_fp16(const __half* __restrict__ A, const __half* __restrict__ B,
               float* __restrict__ C, const float* __restrict__ bias,
               int M, int N, int K)
{
    extern __shared__ char smem[];
    const uint32_t sb = smem_u32(smem);
    const int tid  = threadIdx.x;
    const int wid  = tid >> 5;
    const int lane = tid & 31;
    const int bm = blockIdx.y * BM;
    const int bn = blockIdx.x * BN;
    const int wm = (wid & 3) * 32;    // warp m offset (4 groups over 128)
    const int wn = (wid >> 2) * 64;   // warp n offset (4 groups over 256)
    const int nchunk = K / BK;

    const __half* Abase = A + (size_t)bm * K;
    const __half* Bbase = B + (size_t)bn * K;

    // ---- async tile loader ----
    // 512 threads; granule = 16B (8 halves). A: 128 rows; B: 256 rows.
    const int lg  = tid & 7;          // granule 0..7 within 128B row
    const int lr0 = tid >> 3;         // row 0..63 (+j*64)
    auto load_chunk = [&](int st, int c) {
        const uint32_t stbase = sb + st * STAGE_B;
        {
            const uint32_t dbase = stbase + OFF_A;
            const __half* s = Abase + (size_t)c * BK + lg * 8;
            #pragma unroll
            for (int j = 0; j < 2; j++) {
                const int r = lr0 + j * 64;
                CP_ASYNC16(dbase + r * 128 + ((lg ^ (r & 7)) << 4),
                           s + (size_t)r * K);
            }
        }
        {
            const uint32_t dbase = stbase + OFF_B;
            const __half* s = Bbase + (size_t)c * BK + lg * 8;
            #pragma unroll
            for (int j = 0; j < 4; j++) {
                const int r = lr0 + j * 64;
                CP_ASYNC16(dbase + r * 128 + ((lg ^ (r & 7)) << 4),
                           s + (size_t)r * K);
            }
        }
        CP_COMMIT();
    };

    float acc[2][8][4];
    #pragma unroll
    for (int mi = 0; mi < 2; mi++)
        #pragma unroll
        for (int ni = 0; ni < 8; ni++)
            #pragma unroll
            for (int v = 0; v < 4; v++) acc[mi][ni][v] = 0.f;

    load_chunk(0, 0);
    load_chunk(1, 1);

    // ldmatrix lane addressing (constant per thread, within a k-step)
    const int a_row = wm + (lane & 15);                      // + mi*16
    const int a_kg  = lane >> 4;                             // +2*kk
    const int b_row = wn + (lane & 7) + ((lane >> 4) << 3);  // + p*16
    const int b_kg  = (lane >> 3) & 1;                       // +2*kk

    int st = 0;
    for (int c = 0; c < nchunk; c++) {
        if (c + 1 < nchunk) { CP_WAIT(1); } else { CP_WAIT(0); }
        __syncthreads();
        // prefetch chunk c+2 into the buffer freed by chunk c-1
        if (c + 2 < nchunk) {
            int st2 = st + 2; if (st2 >= NSTAGE) st2 -= NSTAGE;
            load_chunk(st2, c + 2);
        }

        const uint32_t stb = sb + st * STAGE_B;
        const uint32_t sA  = stb + OFF_A;
        const uint32_t sB  = stb + OFF_B;

        #pragma unroll
        for (int kk = 0; kk < 4; kk++) {           // 4 x k16 per chunk
            uint32_t av[2][4];
            #pragma unroll
            for (int mi = 0; mi < 2; mi++) {
                const int r = a_row + mi * 16;
                const int kg = 2 * kk + a_kg;
                LDSM4(av[mi], sA + r * 128 + ((kg ^ (r & 7)) << 4));
            }
            uint32_t bv[8][2];
            #pragma unroll
            for (int p = 0; p < 4; p++) {          // pair of n8 tiles per x4
                const int r = b_row + p * 16;
                const int kg = 2 * kk + b_kg;
                uint32_t t[4];
                LDSM4(t, sB + r * 128 + ((kg ^ (r & 7)) << 4));
                bv[p * 2][0] = t[0]; bv[p * 2][1] = t[1];
                bv[p * 2 + 1][0] = t[2]; bv[p * 2 + 1][1] = t[3];
            }
            #pragma unroll
            for (int mi = 0; mi < 2; mi++)
                #pragma unroll
                for (int ni = 0; ni < 8; ni++)
                    mma16816(acc[mi][ni], av[mi], bv[ni]);
        }
        st++; if (st >= NSTAGE) st = 0;
    }

    // ---- epilogue ----
    const int erow  = bm + wm + (lane >> 2);
    const int ecol0 = bn + wn + (lane & 3) * 2;
    #pragma unroll
    for (int mi = 0; mi < 2; mi++) {
        #pragma unroll
        for (int ni = 0; ni < 8; ni++) {
            const int row = erow + mi * 16;
            const int col = ecol0 + ni * 8;
            float v[4] = { acc[mi][ni][0], acc[mi][ni][1],
                           acc[mi][ni][2], acc[mi][ni][3] };
            if (EPI == 1) {
                #pragma unroll
                for (int q = 0; q < 4; q++) v[q] = fmaxf(v[q], 0.f);
            }
            if (EPI == 2) {
                #pragma unroll
                for (int q = 0; q < 4; q++) v[q] = fmaxf(v[q], 0.f) * SCALE_Q;
            }
            if (EPI == 3) {
                const float b0 = __ldg(&bias[col]), b1 = __ldg(&bias[col + 1]);
                v[0] += b0; v[1] += b1; v[2] += b0; v[3] += b1;
            }
            *reinterpret_cast<float2*>(C + (size_t)row * N + col) =
                make_float2(v[0], v[1]);
            *reinterpret_cast<float2*>(C + (size_t)(row + 8) * N + col) =
                make_float2(v[2], v[3]);
        }
    }
}

// ---------------------------------------------------------------------------
// Conversion kernels
// ---------------------------------------------------------------------------
__global__ __launch_bounds__(256)
void cvt_fp16(const float* __restrict__ in, __half* __restrict__ out, int n)
{
    const int i = (blockIdx.x * 256 + threadIdx.x) * 4;
    if (i >= n) return;
    const float4 v = *reinterpret_cast<const float4*>(in + i);
    __half2* po = reinterpret_cast<__half2*>(out + i);
    po[0] = __floats2half2_rn(v.x, v.y);
    po[1] = __floats2half2_rn(v.z, v.w);
}

// W[K][N] fp32 -> T[N][K] fp16 (transpose + convert)
__global__ __launch_bounds__(256)
void transpose_cvt(const float* __restrict__ W, __half* __restrict__ T,
                   int K, int N)
{
    __shared__ float tile[32][33];
    const int n0 = blockIdx.x * 32, k0 = blockIdx.y * 32;
    const int tx = threadIdx.x, ty = threadIdx.y;
    #pragma unroll
    for (int j = 0; j < 4; j++)
        tile[ty + j * 8][tx] = W[(size_t)(k0 + ty + j * 8) * N + n0 + tx];
    __syncthreads();
    #pragma unroll
    for (int j = 0; j < 4; j++) {
        const int n = n0 + ty + j * 8, k = k0 + tx;
        T[(size_t)n * K + k] = __float2half_rn(tile[tx][ty + j * 8]);
    }
}

// ---------------------------------------------------------------------------
// Per-token stage, 4x4 register-blocked; emits fp16 directly.
//   w[d] = sum_i k[i,d];  qw = q*w;  norm[i] = sum_d qw[i,d]
//   mid[i,j] = sum_d qw[i,d]*v[j,d] / (norm[i]+eps)
// ---------------------------------------------------------------------------
__global__ __launch_bounds__(256)
void perf_mid_kernel()
{
    __shared__ float sq[64 * 65];
    __shared__ float sv[64 * 65];
    __shared__ float w[64];
    __shared__ float rnorm[64];

    const int t   = blockIdx.x;
    const int tid = threadIdx.x;
    const float* qt = g_q + (size_t)t * INNER;
    const float* kt = g_k + (size_t)t * INNER;
    const float* vt = g_v + (size_t)t * INNER;

    for (int idx = tid; idx < 4096; idx += 256) {
        const int i = idx >> 6, d = idx & 63;
        sq[i * 65 + d] = qt[idx];
        sv[i * 65 + d] = vt[idx];
    }
    if (tid < 64) {
        float s = 0.f;
        #pragma unroll 8
        for (int i = 0; i < 64; i++) s += kt[i * 64 + tid];
        w[tid] = s;
    }
    __syncthreads();

    for (int idx = tid; idx < 4096; idx += 256) {
        const int i = idx >> 6, d = idx & 63;
        sq[i * 65 + d] *= w[d];
    }
    __syncthreads();

    if (tid < 64) {
        float s = 0.f;
        #pragma unroll 8
        for (int d = 0; d < 64; d++) s += sq[tid * 65 + d];
        rnorm[tid] = 1.f / (s + EPS);
    }
    __syncthreads();

    const int ti = tid >> 4, tj = tid & 15;
    const int i0 = ti * 4, j0 = tj * 4;
    float acc[4][4];
    #pragma unroll
    for (int r = 0; r < 4; r++)
        #pragma unroll
        for (int c = 0; c < 4; c++) acc[r][c] = 0.f;

    #pragma unroll 4
    for (int d = 0; d < 64; d++) {
        float a[4], b[4];
        #pragma unroll
        for (int r = 0; r < 4; r++) a[r] = sq[(i0 + r) * 65 + d];
        #pragma unroll
        for (int c = 0; c < 4; c++) b[c] = sv[(j0 + c) * 65 + d];
        #pragma unroll
        for (int r = 0; r < 4; r++)
            #pragma unroll
            for (int c = 0; c < 4; c++) acc[r][c] += a[r] * b[c];
    }

    __half* mo = g_m + (size_t)t * INNER;
    #pragma unroll
    for (int r = 0; r < 4; r++) {
        const int i = i0 + r;
        const float rn_ = rnorm[i];
        __half2* po = reinterpret_cast<__half2*>(mo + i * 64 + j0);
        po[0] = __floats2half2_rn(acc[r][0] * rn_, acc[r][1] * rn_);
        po[1] = __floats2half2_rn(acc[r][2] * rn_, acc[r][3] * rn_);
    }
}

// ---------------------------------------------------------------------------
extern "C" void kernel_launch(void* const* d_in, const int* in_sizes, int n_in,
                              void* d_out, int out_size)
{
    const float* x  = (const float*)d_in[0];
    const float* Wq = (const float*)d_in[1];
    const float* Wk = (const float*)d_in[2];
    const float* Wv = (const float*)d_in[3];
    const float* Wo = (const float*)d_in[4];
    const float* bo = (const float*)d_in[5];
    float* out = (float*)d_out;

    __half *xh, *wq, *wk, *wv, *wo, *mp;
    float *qp, *kp, *vp;
    cudaGetSymbolAddress((void**)&xh, g_xh);
    cudaGetSymbolAddress((void**)&wq, g_wq);
    cudaGetSymbolAddress((void**)&wk, g_wk);
    cudaGetSymbolAddress((void**)&wv, g_wv);
    cudaGetSymbolAddress((void**)&wo, g_wo);
    cudaGetSymbolAddress((void**)&mp, g_m);
    cudaGetSymbolAddress((void**)&qp, g_q);
    cudaGetSymbolAddress((void**)&kp, g_k);
    cudaGetSymbolAddress((void**)&vp, g_v);

    cudaFuncSetAttribute(gemm_fp16<0>, cudaFuncAttributeMaxDynamicSharedMemorySize, GEMM_SMEM);
    cudaFuncSetAttribute(gemm_fp16<1>, cudaFuncAttributeMaxDynamicSharedMemorySize, GEMM_SMEM);
    cudaFuncSetAttribute(gemm_fp16<2>, cudaFuncAttributeMaxDynamicSharedMemorySize, GEMM_SMEM);
    cudaFuncSetAttribute(gemm_fp16<3>, cudaFuncAttributeMaxDynamicSharedMemorySize, GEMM_SMEM);

    // Stage 0: fp16 conversions
    cvt_fp16<<<(MTOK * DIM) / 1024, 256>>>(x, xh, MTOK * DIM);
    dim3 tb(32, 8);
    transpose_cvt<<<dim3(INNER / 32, DIM / 32), tb>>>(Wq, wq, DIM, INNER);
    transpose_cvt<<<dim3(INNER / 32, DIM / 32), tb>>>(Wk, wk, DIM, INNER);
    transpose_cvt<<<dim3(INNER / 32, DIM / 32), tb>>>(Wv, wv, DIM, INNER);
    transpose_cvt<<<dim3(DIM / 32, INNER / 32), tb>>>(Wo, wo, INNER, DIM);

    // Stage 1: QKV projections (HMMA fp16) with fused activations
    dim3 gQKV(INNER / BN, MTOK / BM);   // 16 x 64
    gemm_fp16<2><<<gQKV, 512, GEMM_SMEM>>>(xh, wq, qp, nullptr, MTOK, INNER, DIM);
    gemm_fp16<1><<<gQKV, 512, GEMM_SMEM>>>(xh, wk, kp, nullptr, MTOK, INNER, DIM);
    gemm_fp16<0><<<gQKV, 512, GEMM_SMEM>>>(xh, wv, vp, nullptr, MTOK, INNER, DIM);

    // Stage 2: per-token collapsed attention (emits fp16 mid)
    perf_mid_kernel<<<MTOK, 256>>>();

    // Stage 3: output projection + bias
    dim3 gOut(DIM / BN, MTOK / BM);     // 4 x 64
    gemm_fp16<3><<<gOut, 512, GEMM_SMEM>>>(mp, wo, out, bo, MTOK, DIM, INNER);
}

// round 17
// speedup vs baseline: 6.9666x; 1.0058x over previous
#include <cuda_runtime.h>
#include <cuda_fp16.h>
#include <cstdint>

// ---------------------------------------------------------------------------
// Problem constants
// ---------------------------------------------------------------------------
#define BATCH   2
#define SEQ     4096
#define DIM     1024
#define NHEADS  64
#define DHEAD   64
#define INNER   (NHEADS * DHEAD)     // 4096
#define MTOK    (BATCH * SEQ)        // 8192
#define SCALE_Q 0.125f
#define EPS     1e-6f

// ---------------------------------------------------------------------------
// Device scratch (static globals allowed; runtime allocation is not)
// ---------------------------------------------------------------------------
__device__ __align__(128) __half g_xh[(size_t)MTOK * DIM];
__device__ __align__(128) __half g_wq[(size_t)INNER * DIM];   // [N][K]
__device__ __align__(128) __half g_wk[(size_t)INNER * DIM];
__device__ __align__(128) __half g_wv[(size_t)INNER * DIM];
__device__ __align__(128) __half g_wo[(size_t)DIM * INNER];   // [1024][4096]
__device__ __align__(128) float g_q[(size_t)MTOK * INNER];
__device__ __align__(128) float g_k[(size_t)MTOK * INNER];
__device__ __align__(128) float g_v[(size_t)MTOK * INNER];
__device__ __align__(128) __half g_m[(size_t)MTOK * INNER];

// ---------------------------------------------------------------------------
// PTX helpers (plain sm_80+/sm_75+ — no 'a'-features; sm_103 target safe)
// ---------------------------------------------------------------------------
__device__ __forceinline__ uint32_t smem_u32(const void* p) {
    uint32_t a;
    asm("{ .reg .u64 t; cvta.to.shared.u64 t, %1; cvt.u32.u64 %0, t; }"
        : "=r"(a) : "l"(p));
    return a;
}

#define CP_ASYNC16(dst, src) \
    asm volatile("cp.async.cg.shared.global [%0], [%1], 16;" :: "r"(dst), "l"(src) : "memory")
#define CP_COMMIT() asm volatile("cp.async.commit_group;" ::: "memory")
#define CP_WAIT(n)  asm volatile("cp.async.wait_group %0;" :: "n"(n) : "memory")

#define LDSM4(r, addr) \
    asm volatile("ldmatrix.sync.aligned.m8n8.x4.shared.b16 {%0,%1,%2,%3}, [%4];" \
        : "=r"((r)[0]), "=r"((r)[1]), "=r"((r)[2]), "=r"((r)[3]) : "r"(addr))

__device__ __forceinline__ void mma16816(float* d, const uint32_t* a, const uint32_t* b) {
    asm volatile(
        "mma.sync.aligned.m16n8k16.row.col.f32.f16.f16.f32 "
        "{%0,%1,%2,%3}, {%4,%5,%6,%7}, {%8,%9}, {%0,%1,%2,%3};"
        : "+f"(d[0]), "+f"(d[1]), "+f"(d[2]), "+f"(d[3])
        : "r"(a[0]), "r"(a[1]), "r"(a[2]), "r"(a[3]), "r"(b[0]), "r"(b[1]));
}

// ---------------------------------------------------------------------------
// fp16 GEMM on HMMA (mma.sync):  C[M,N] fp32 = A[M,K] @ B[N,K]^T
// BM=128, BN=256, BK=64 (128B swizzled rows), 3-stage cp.async pipeline.
// 512 threads, 16 warps as 4(m) x 4(n); warp tile 32x64.
// EPI: 0 identity, 1 relu, 2 relu*SCALE_Q, 3 +bias
// ---------------------------------------------------------------------------
#define BM 128
#define BN 256
#define BK 64
#define TILE_A_B (128 * 128)          // 16384 bytes (128 rows x 128B)
#define TILE_B_B (256 * 128)          // 32768 bytes (256 rows x 128B)
#define OFF_A 0
#define OFF_B (TILE_A_B)
#define STAGE_B (TILE_A_B + TILE_B_B)           // 49152
#define NSTAGE 3
#define GEMM_SMEM (NSTAGE * STAGE_B)            // 147456

template<int EPI>
__global__ __launch_bounds__(512, 1)
void gemm_fp16(const __half* __restrict__ A, const __half* __restrict__ B,
               float* __restrict__ C, const float* __restrict__ bias,
               int M, int N, int K)
{
    extern __shared__ char smem[];
    const uint32_t sb = smem_u32(smem);
    const int tid  = threadIdx.x;
    const int wid  = tid >> 5;
    const int lane = tid & 31;
    const int bm = blockIdx.y * BM;
    const int bn = blockIdx.x * BN;
    const int wm = (wid & 3) * 32;    // warp m offset (4 groups over 128)
    const int wn = (wid >> 2) * 64;   // warp n offset (4 groups over 256)
    const int nchunk = K / BK;

    const __half* Abase = A + (size_t)bm * K;
    const __half* Bbase = B + (size_t)bn * K;

    // ---- async tile loader ----
    // 512 threads; granule = 16B (8 halves). A: 128 rows; B: 256 rows.
    const int lg  = tid & 7;          // granule 0..7 within 128B row
    const int lr0 = tid >> 3;         // row 0..63 (+j*64)
    auto load_chunk = [&](int st, int c) {
        const uint32_t stbase = sb + st * STAGE_B;
        {
            const uint32_t dbase = stbase + OFF_A;
            const __half* s = Abase + (size_t)c * BK + lg * 8;
            #pragma unroll
            for (int j = 0; j < 2; j++) {
                const int r = lr0 + j * 64;
                CP_ASYNC16(dbase + r * 128 + ((lg ^ (r & 7)) << 4),
                           s + (size_t)r * K);
            }
        }
        {
            const uint32_t dbase = stbase + OFF_B;
            const __half* s = Bbase + (size_t)c * BK + lg * 8;
            #pragma unroll
            for (int j = 0; j < 4; j++) {
                const int r = lr0 + j * 64;
                CP_ASYNC16(dbase + r * 128 + ((lg ^ (r & 7)) << 4),
                           s + (size_t)r * K);
            }
        }
        CP_COMMIT();
    };

    float acc[2][8][4];
    #pragma unroll
    for (int mi = 0; mi < 2; mi++)
        #pragma unroll
        for (int ni = 0; ni < 8; ni++)
            #pragma unroll
            for (int v = 0; v < 4; v++) acc[mi][ni][v] = 0.f;

    load_chunk(0, 0);
    load_chunk(1, 1);

    // ldmatrix lane addressing (constant per thread, within a k-step)
    const int a_row = wm + (lane & 15);                      // + mi*16
    const int a_kg  = lane >> 4;                             // +2*kk
    const int b_row = wn + (lane & 7) + ((lane >> 4) << 3);  // + p*16
    const int b_kg  = (lane >> 3) & 1;                       // +2*kk

    int st = 0;
    for (int c = 0; c < nchunk; c++) {
        if (c + 1 < nchunk) { CP_WAIT(1); } else { CP_WAIT(0); }
        __syncthreads();
        // prefetch chunk c+2 into the buffer freed by chunk c-1
        if (c + 2 < nchunk) {
            int st2 = st + 2; if (st2 >= NSTAGE) st2 -= NSTAGE;
            load_chunk(st2, c + 2);
        }

        const uint32_t stb = sb + st * STAGE_B;
        const uint32_t sA  = stb + OFF_A;
        const uint32_t sB  = stb + OFF_B;

        #pragma unroll
        for (int kk = 0; kk < 4; kk++) {           // 4 x k16 per chunk
            uint32_t av[2][4];
            #pragma unroll
            for (int mi = 0; mi < 2; mi++) {
                const int r = a_row + mi * 16;
                const int kg = 2 * kk + a_kg;
                LDSM4(av[mi], sA + r * 128 + ((kg ^ (r & 7)) << 4));
            }
            uint32_t bv[8][2];
            #pragma unroll
            for (int p = 0; p < 4; p++) {          // pair of n8 tiles per x4
                const int r = b_row + p * 16;
                const int kg = 2 * kk + b_kg;
                uint32_t t[4];
                LDSM4(t, sB + r * 128 + ((kg ^ (r & 7)) << 4));
                bv[p * 2][0] = t[0]; bv[p * 2][1] = t[1];
                bv[p * 2 + 1][0] = t[2]; bv[p * 2 + 1][1] = t[3];
            }
            #pragma unroll
            for (int mi = 0; mi < 2; mi++)
                #pragma unroll
                for (int ni = 0; ni < 8; ni++)
                    mma16816(acc[mi][ni], av[mi], bv[ni]);
        }
        st++; if (st >= NSTAGE) st = 0;
    }

    // ---- epilogue ----
    const int erow  = bm + wm + (lane >> 2);
    const int ecol0 = bn + wn + (lane & 3) * 2;
    #pragma unroll
    for (int mi = 0; mi < 2; mi++) {
        #pragma unroll
        for (int ni = 0; ni < 8; ni++) {
            const int row = erow + mi * 16;
            const int col = ecol0 + ni * 8;
            float v[4] = { acc[mi][ni][0], acc[mi][ni][1],
                           acc[mi][ni][2], acc[mi][ni][3] };
            if (EPI == 1) {
                #pragma unroll
                for (int q = 0; q < 4; q++) v[q] = fmaxf(v[q], 0.f);
            }
            if (EPI == 2) {
                #pragma unroll
                for (int q = 0; q < 4; q++) v[q] = fmaxf(v[q], 0.f) * SCALE_Q;
            }
            if (EPI == 3) {
                const float b0 = __ldg(&bias[col]), b1 = __ldg(&bias[col + 1]);
                v[0] += b0; v[1] += b1; v[2] += b0; v[3] += b1;
            }
            *reinterpret_cast<float2*>(C + (size_t)row * N + col) =
                make_float2(v[0], v[1]);
            *reinterpret_cast<float2*>(C + (size_t)(row + 8) * N + col) =
                make_float2(v[2], v[3]);
        }
    }
}

// ---------------------------------------------------------------------------
// Conversion kernels
// ---------------------------------------------------------------------------
__global__ __launch_bounds__(256)
void cvt_fp16(const float* __restrict__ in, __half* __restrict__ out, int n)
{
    const int i = (blockIdx.x * 256 + threadIdx.x) * 4;
    if (i >= n) return;
    const float4 v = *reinterpret_cast<const float4*>(in + i);
    __half2* po = reinterpret_cast<__half2*>(out + i);
    po[0] = __floats2half2_rn(v.x, v.y);
    po[1] = __floats2half2_rn(v.z, v.w);
}

// W[K][N] fp32 -> T[N][K] fp16 (transpose + convert)
__global__ __launch_bounds__(256)
void transpose_cvt(const float* __restrict__ W, __half* __restrict__ T,
                   int K, int N)
{
    __shared__ float tile[32][33];
    const int n0 = blockIdx.x * 32, k0 = blockIdx.y * 32;
    const int tx = threadIdx.x, ty = threadIdx.y;
    #pragma unroll
    for (int j = 0; j < 4; j++)
        tile[ty + j * 8][tx] = W[(size_t)(k0 + ty + j * 8) * N + n0 + tx];
    __syncthreads();
    #pragma unroll
    for (int j = 0; j < 4; j++) {
        const int n = n0 + ty + j * 8, k = k0 + tx;
        T[(size_t)n * K + k] = __float2half_rn(tile[tx][ty + j * 8]);
    }
}

// ---------------------------------------------------------------------------
// Per-token stage, 4x4 register-blocked; emits fp16 directly.
//   w[d] = sum_i k[i,d];  qw = q*w;  norm[i] = sum_d qw[i,d]
//   mid[i,j] = sum_d qw[i,d]*v[j,d] / (norm[i]+eps)
// ---------------------------------------------------------------------------
__global__ __launch_bounds__(256)
void perf_mid_kernel()
{
    __shared__ float sq[64 * 65];
    __shared__ float sv[64 * 65];
    __shared__ float w[64];
    __shared__ float rnorm[64];

    const int t   = blockIdx.x;
    const int tid = threadIdx.x;
    const float* qt = g_q + (size_t)t * INNER;
    const float* kt = g_k + (size_t)t * INNER;
    const float* vt = g_v + (size_t)t * INNER;

    for (int idx = tid; idx < 4096; idx += 256) {
        const int i = idx >> 6, d = idx & 63;
        sq[i * 65 + d] = qt[idx];
        sv[i * 65 + d] = vt[idx];
    }
    if (tid < 64) {
        float s = 0.f;
        #pragma unroll 8
        for (int i = 0; i < 64; i++) s += kt[i * 64 + tid];
        w[tid] = s;
    }
    __syncthreads();

    for (int idx = tid; idx < 4096; idx += 256) {
        const int i = idx >> 6, d = idx & 63;
        sq[i * 65 + d] *= w[d];
    }
    __syncthreads();

    if (tid < 64) {
        float s = 0.f;
        #pragma unroll 8
        for (int d = 0; d < 64; d++) s += sq[tid * 65 + d];
        rnorm[tid] = 1.f / (s + EPS);
    }
    __syncthreads();

    const int ti = tid >> 4, tj = tid & 15;
    const int i0 = ti * 4, j0 = tj * 4;
    float acc[4][4];
    #pragma unroll
    for (int r = 0; r < 4; r++)
        #pragma unroll
        for (int c = 0; c < 4; c++) acc[r][c] = 0.f;

    #pragma unroll 4
    for (int d = 0; d < 64; d++) {
        float a[4], b[4];
        #pragma unroll
        for (int r = 0; r < 4; r++) a[r] = sq[(i0 + r) * 65 + d];
        #pragma unroll
        for (int c = 0; c < 4; c++) b[c] = sv[(j0 + c) * 65 + d];
        #pragma unroll
        for (int r = 0; r < 4; r++)
            #pragma unroll
            for (int c = 0; c < 4; c++) acc[r][c] += a[r] * b[c];
    }

    __half* mo = g_m + (size_t)t * INNER;
    #pragma unroll
    for (int r = 0; r < 4; r++) {
        const int i = i0 + r;
        const float rn_ = rnorm[i];
        __half2* po = reinterpret_cast<__half2*>(mo + i * 64 + j0);
        po[0] = __floats2half2_rn(acc[r][0] * rn_, acc[r][1] * rn_);
        po[1] = __floats2half2_rn(acc[r][2] * rn_, acc[r][3] * rn_);
    }
}

// ---------------------------------------------------------------------------
extern "C" void kernel_launch(void* const* d_in, const int* in_sizes, int n_in,
                              void* d_out, int out_size)
{
    const float* x  = (const float*)d_in[0];
    const float* Wq = (const float*)d_in[1];
    const float* Wk = (const float*)d_in[2];
    const float* Wv = (const float*)d_in[3];
    const float* Wo = (const float*)d_in[4];
    const float* bo = (const float*)d_in[5];
    float* out = (float*)d_out;

    __half *xh, *wq, *wk, *wv, *wo, *mp;
    float *qp, *kp, *vp;
    cudaGetSymbolAddress((void**)&xh, g_xh);
    cudaGetSymbolAddress((void**)&wq, g_wq);
    cudaGetSymbolAddress((void**)&wk, g_wk);
    cudaGetSymbolAddress((void**)&wv, g_wv);
    cudaGetSymbolAddress((void**)&wo, g_wo);
    cudaGetSymbolAddress((void**)&mp, g_m);
    cudaGetSymbolAddress((void**)&qp, g_q);
    cudaGetSymbolAddress((void**)&kp, g_k);
    cudaGetSymbolAddress((void**)&vp, g_v);

    cudaFuncSetAttribute(gemm_fp16<0>, cudaFuncAttributeMaxDynamicSharedMemorySize, GEMM_SMEM);
    cudaFuncSetAttribute(gemm_fp16<1>, cudaFuncAttributeMaxDynamicSharedMemorySize, GEMM_SMEM);
    cudaFuncSetAttribute(gemm_fp16<2>, cudaFuncAttributeMaxDynamicSharedMemorySize, GEMM_SMEM);
    cudaFuncSetAttribute(gemm_fp16<3>, cudaFuncAttributeMaxDynamicSharedMemorySize, GEMM_SMEM);

    // Stage 0: fp16 conversions
    cvt_fp16<<<(MTOK * DIM) / 1024, 256>>>(x, xh, MTOK * DIM);
    dim3 tb(32, 8);
    transpose_cvt<<<dim3(INNER / 32, DIM / 32), tb>>>(Wq, wq, DIM, INNER);
    transpose_cvt<<<dim3(INNER / 32, DIM / 32), tb>>>(Wk, wk, DIM, INNER);
    transpose_cvt<<<dim3(INNER / 32, DIM / 32), tb>>>(Wv, wv, DIM, INNER);
    transpose_cvt<<<dim3(DIM / 32, INNER / 32), tb>>>(Wo, wo, INNER, DIM);

    // Stage 1: QKV projections (HMMA fp16) with fused activations
    dim3 gQKV(INNER / BN, MTOK / BM);   // 16 x 64
    gemm_fp16<2><<<gQKV, 512, GEMM_SMEM>>>(xh, wq, qp, nullptr, MTOK, INNER, DIM);
    gemm_fp16<1><<<gQKV, 512, GEMM_SMEM>>>(xh, wk, kp, nullptr, MTOK, INNER, DIM);
    gemm_fp16<0><<<gQKV, 512, GEMM_SMEM>>>(xh, wv, vp, nullptr, MTOK, INNER, DIM);

    // Stage 2: per-token collapsed attention (emits fp16 mid)
    perf_mid_kernel<<<MTOK, 256>>>();

    // Stage 3: output projection + bias
    dim3 gOut(DIM / BN, MTOK / BM);     // 4 x 64
    gemm_fp16<3><<<gOut, 512, GEMM_SMEM>>>(mp, wo, out, bo, MTOK, DIM, INNER);
}